// round 3
// baseline (speedup 1.0000x reference)
#include <cuda_runtime.h>

#define C_DIM 512
#define L_DIM 2048
#define BATCH 4
#define HEADS 8
#define HDIM 64

using u64 = unsigned long long;

__device__ __forceinline__ u64 ffma2(u64 a, u64 b, u64 c) {
    u64 d; asm("fma.rn.f32x2 %0, %1, %2, %3;" : "=l"(d) : "l"(a), "l"(b), "l"(c)); return d;
}
__device__ __forceinline__ float2 upk(u64 v) {
    float2 f; asm("mov.b64 {%0, %1}, %2;" : "=f"(f.x), "=f"(f.y) : "l"(v)); return f;
}
__device__ __forceinline__ float ex2f_(float x) {
    float r; asm("ex2.approx.f32 %0, %1;" : "=f"(r) : "f"(x)); return r;
}

// Scratch (allocation-free rule: __device__ globals)
__device__ float g_qkv[BATCH * 3 * C_DIM * L_DIM]; // [B,3C,L]
__device__ float g_att[BATCH * C_DIM * L_DIM];     // attention out [B,C,L]
__device__ float g_z[BATCH * C_DIM * L_DIM];       // proj + bias + residual

// ---------------------------------------------------------------------------
// Tiled SGEMM with packed f32x2 FMA.
// BM=BN=128, BK=8, 256 threads, 8x8 microtile computed as 8x4 pair-tiles.
// A tile stored DUPLICATED in smem so (a,a) pairs come free from LDS.128.
// ---------------------------------------------------------------------------
template<bool CLIP, bool RES>
__global__ __launch_bounds__(256, 2) void sgemm_kernel(
    const float* __restrict__ A, const float* __restrict__ B, float* __restrict__ Cmat,
    const float* __restrict__ bias, const float* __restrict__ res,
    int M, int N, int K, int strideB, int strideC)
{
    __shared__ float As2[8][256];   // k-major, m duplicated: [k][2m]=[k][2m+1]=A[m][k]
    __shared__ float Bs[8][128];
    const int t = threadIdx.x;
    const int tx = t & 15, ty = t >> 4;
    const int n0 = blockIdx.x * 128, m0 = blockIdx.y * 128;
    const float* Bp = B + (size_t)blockIdx.z * strideB;
    float* Cp = Cmat + (size_t)blockIdx.z * strideC;
    const float* Rp = RES ? (res + (size_t)blockIdx.z * strideB) : nullptr;

    const int arow = t >> 1, acol = (t & 1) * 4;
    const int brow = t >> 5, bcol = (t & 31) * 4;
    const float* Aptr = A + (size_t)(m0 + arow) * K + acol;
    const float* Bptr = Bp + (size_t)brow * N + n0 + bcol;

    u64 acc2[8][4] = {};
    for (int k0 = 0; k0 < K; k0 += 8) {
        float4 av = *(const float4*)(Aptr + k0);
        float4 bv = *(const float4*)(Bptr + (size_t)k0 * N);
        {   // duplicated store: As2[acol+i][2*arow .. 2*arow+1] = a
            float2 d0 = {av.x, av.x}, d1 = {av.y, av.y}, d2 = {av.z, av.z}, d3 = {av.w, av.w};
            ((float2*)As2[acol + 0])[arow] = d0;
            ((float2*)As2[acol + 1])[arow] = d1;
            ((float2*)As2[acol + 2])[arow] = d2;
            ((float2*)As2[acol + 3])[arow] = d3;
        }
        *(float4*)&Bs[brow][bcol] = bv;
        __syncthreads();
        #pragma unroll
        for (int kk = 0; kk < 8; kk++) {
            u64 ap[8], bp[4];
            *(uint4*)&ap[0] = *(const uint4*)&As2[kk][8 * ty];            // rows 4ty..+1
            *(uint4*)&ap[2] = *(const uint4*)&As2[kk][8 * ty + 4];        // rows 4ty+2..+3
            *(uint4*)&ap[4] = *(const uint4*)&As2[kk][128 + 8 * ty];      // rows 64+4ty..
            *(uint4*)&ap[6] = *(const uint4*)&As2[kk][128 + 8 * ty + 4];
            *(uint4*)&bp[0] = *(const uint4*)&Bs[kk][tx * 4];             // cols tx*4..+3
            *(uint4*)&bp[2] = *(const uint4*)&Bs[kk][64 + tx * 4];        // cols 64+tx*4..
            #pragma unroll
            for (int r = 0; r < 8; r++)
                #pragma unroll
                for (int c = 0; c < 4; c++)
                    acc2[r][c] = ffma2(ap[r], bp[c], acc2[r][c]);
        }
        __syncthreads();
    }

    #pragma unroll
    for (int r = 0; r < 8; r++) {
        int m = m0 + (r >> 2) * 64 + ty * 4 + (r & 3);
        float bvl = bias[m];
        #pragma unroll
        for (int ch = 0; ch < 2; ch++) {
            int n = n0 + ch * 64 + tx * 4;
            float2 e0 = upk(acc2[r][2 * ch + 0]);
            float2 e1 = upk(acc2[r][2 * ch + 1]);
            float4 o;
            o.x = e0.x + bvl; o.y = e0.y + bvl; o.z = e1.x + bvl; o.w = e1.y + bvl;
            if (CLIP) {
                o.x = fminf(10.f, fmaxf(-10.f, o.x));
                o.y = fminf(10.f, fmaxf(-10.f, o.y));
                o.z = fminf(10.f, fmaxf(-10.f, o.z));
                o.w = fminf(10.f, fmaxf(-10.f, o.w));
            }
            if (RES) {
                float4 rv = *(const float4*)(Rp + (size_t)m * N + n);
                o.x += rv.x; o.y += rv.y; o.z += rv.z; o.w += rv.w;
            }
            *(float4*)(Cp + (size_t)m * N + n) = o;
        }
    }
}

// ---------------------------------------------------------------------------
// Flash-style attention, packed f32x2. Block = 64 queries of one (b,h).
// Clip before softmax => exp bounded => no online max, denominators at end.
// Dynamic smem (80KB): Q dup [64][128], KV [64][64], P dup [64][128].
// ---------------------------------------------------------------------------
__global__ __launch_bounds__(256) void attn_kernel(
    const float* __restrict__ qkv, float* __restrict__ outp)
{
    extern __shared__ float sm[];
    float* qs2 = sm;                 // [d][2i] duplicated over i
    float* kv  = sm + 64 * 128;      // K: [d][j]; later V^T: [j][d]
    float* ps2 = kv + 64 * 64;       // [i][2j] duplicated over j

    const int t = threadIdx.x;
    const int tx = t & 15, ty = t >> 4;
    const int b = blockIdx.z, h = blockIdx.y;
    const int i0 = blockIdx.x * 64;
    const float* qp = qkv + ((size_t)(b * 3 * C_DIM) + h * HDIM) * L_DIM;
    const float* kp = qp + (size_t)C_DIM * L_DIM;
    const float* vp = qp + (size_t)2 * C_DIM * L_DIM;

    // Q tile duplicated: qs2[d][2i],[2i+1] = Q[d][i0+i]
    {
        int lr = t >> 4, lc = (t & 15) * 4;
        #pragma unroll
        for (int it = 0; it < 4; it++) {
            int d = lr + it * 16;
            float4 v = *(const float4*)&qp[(size_t)d * L_DIM + i0 + lc];
            float4 w0 = {v.x, v.x, v.y, v.y};
            float4 w1 = {v.z, v.z, v.w, v.w};
            *(float4*)&qs2[d * 128 + 2 * lc]     = w0;
            *(float4*)&qs2[d * 128 + 2 * lc + 4] = w1;
        }
    }

    float lp[4] = {0.f, 0.f, 0.f, 0.f};
    u64 oacc2[4][2] = {};
    const float K1 = 0.125f * 1.44269504f;   // scale * log2(e)
    const float LIM = 10.f * 1.44269504f;    // clip bound in log2 domain

    for (int j0 = 0; j0 < L_DIM; j0 += 64) {
        __syncthreads(); // prev O-phase done with kv/ps2
        // K tile: kv[d][j]
        {
            int lr = t >> 4, lc = (t & 15) * 4;
            #pragma unroll
            for (int it = 0; it < 4; it++) {
                int d = lr + it * 16;
                *(float4*)&kv[d * 64 + lc] = *(const float4*)&kp[(size_t)d * L_DIM + j0 + lc];
            }
        }
        __syncthreads();

        // S = Q^T K via f32x2 (pairs over j)
        u64 s2[4][2] = {};
        #pragma unroll 8
        for (int d = 0; d < 64; d++) {
            u64 qp2[4], kp2[2];
            *(uint4*)&qp2[0] = *(const uint4*)&qs2[d * 128 + 8 * ty];
            *(uint4*)&qp2[2] = *(const uint4*)&qs2[d * 128 + 8 * ty + 4];
            *(uint4*)&kp2[0] = *(const uint4*)&kv[d * 64 + tx * 4];
            #pragma unroll
            for (int r = 0; r < 4; r++) {
                s2[r][0] = ffma2(qp2[r], kp2[0], s2[r][0]);
                s2[r][1] = ffma2(qp2[r], kp2[1], s2[r][1]);
            }
        }
        // scale+clip+exp (log2 domain), row sums, store P duplicated
        #pragma unroll
        for (int r = 0; r < 4; r++) {
            float2 e0 = upk(s2[r][0]), e1 = upk(s2[r][1]);
            float p0 = ex2f_(fminf(LIM, fmaxf(-LIM, e0.x * K1)));
            float p1 = ex2f_(fminf(LIM, fmaxf(-LIM, e0.y * K1)));
            float p2 = ex2f_(fminf(LIM, fmaxf(-LIM, e1.x * K1)));
            float p3 = ex2f_(fminf(LIM, fmaxf(-LIM, e1.y * K1)));
            lp[r] += p0 + p1 + p2 + p3;
            float4 w0 = {p0, p0, p1, p1};
            float4 w1 = {p2, p2, p3, p3};
            *(float4*)&ps2[(ty * 4 + r) * 128 + 8 * tx]     = w0;
            *(float4*)&ps2[(ty * 4 + r) * 128 + 8 * tx + 4] = w1;
        }
        __syncthreads(); // S reads of kv done; ps2 visible

        // V tile transposed: kv[j][d]
        {
            int dd = t & 63;
            int jc = (t >> 6) * 4;
            #pragma unroll
            for (int it = 0; it < 4; it++) {
                int j = jc + it * 16;
                float4 vv = *(const float4*)&vp[(size_t)dd * L_DIM + j0 + j];
                kv[(j + 0) * 64 + dd] = vv.x;
                kv[(j + 1) * 64 + dd] = vv.y;
                kv[(j + 2) * 64 + dd] = vv.z;
                kv[(j + 3) * 64 + dd] = vv.w;
            }
        }
        __syncthreads();

        // O += P V^T via f32x2 (pairs over d), j unrolled by 2
        #pragma unroll 8
        for (int j = 0; j < 64; j += 2) {
            u64 va[2], vb[2];
            *(uint4*)&va[0] = *(const uint4*)&kv[j * 64 + tx * 4];
            *(uint4*)&vb[0] = *(const uint4*)&kv[(j + 1) * 64 + tx * 4];
            #pragma unroll
            for (int r = 0; r < 4; r++) {
                u64 pp[2];
                *(uint4*)&pp[0] = *(const uint4*)&ps2[(ty * 4 + r) * 128 + 2 * j];
                oacc2[r][0] = ffma2(pp[0], va[0], oacc2[r][0]);
                oacc2[r][1] = ffma2(pp[0], va[1], oacc2[r][1]);
                oacc2[r][0] = ffma2(pp[1], vb[0], oacc2[r][0]);
                oacc2[r][1] = ffma2(pp[1], vb[1], oacc2[r][1]);
            }
        }
    }

    // Row denominators: reduce across 16 tx lanes
    #pragma unroll
    for (int r = 0; r < 4; r++) {
        float v = lp[r];
        #pragma unroll
        for (int o = 8; o; o >>= 1) v += __shfl_xor_sync(0xffffffffu, v, o, 16);
        lp[r] = 1.0f / v;
    }

    // Unpack O and write (4 consecutive i per float4, coalesced runs)
    float oacc[4][4];
    #pragma unroll
    for (int r = 0; r < 4; r++) {
        float2 e0 = upk(oacc2[r][0]), e1 = upk(oacc2[r][1]);
        oacc[r][0] = e0.x; oacc[r][1] = e0.y; oacc[r][2] = e1.x; oacc[r][3] = e1.y;
    }
    float* ob = outp + ((size_t)(b * C_DIM) + h * HDIM) * L_DIM;
    #pragma unroll
    for (int c = 0; c < 4; c++) {
        int d = tx * 4 + c;
        float4 o4;
        o4.x = oacc[0][c] * lp[0];
        o4.y = oacc[1][c] * lp[1];
        o4.z = oacc[2][c] * lp[2];
        o4.w = oacc[3][c] * lp[3];
        *(float4*)&ob[(size_t)d * L_DIM + i0 + ty * 4] = o4;
    }
}

// ---------------------------------------------------------------------------
// GroupNorm over z (residual already fused). One block per (b, group).
// ---------------------------------------------------------------------------
__global__ __launch_bounds__(512) void gn_kernel(
    const float* __restrict__ z, const float* __restrict__ gamma,
    const float* __restrict__ beta, float* __restrict__ outp)
{
    const int bg = blockIdx.x;
    const int b = bg >> 5, g = bg & 31;
    const float* zp = z + ((size_t)b * C_DIM + g * 16) * L_DIM;
    float* op = outp + ((size_t)b * C_DIM + g * 16) * L_DIM;
    const int t = threadIdx.x;

    float s = 0.f, ss = 0.f;
    const float4* z4 = (const float4*)zp;
    for (int i = t; i < 8192; i += 512) {
        float4 v = z4[i];
        s  += v.x + v.y + v.z + v.w;
        ss += v.x * v.x + v.y * v.y + v.z * v.z + v.w * v.w;
    }
    __shared__ float rs[16], rss[16];
    __shared__ float smu, srstd;
    #pragma unroll
    for (int o = 16; o; o >>= 1) {
        s  += __shfl_xor_sync(0xffffffffu, s, o);
        ss += __shfl_xor_sync(0xffffffffu, ss, o);
    }
    if ((t & 31) == 0) { rs[t >> 5] = s; rss[t >> 5] = ss; }
    __syncthreads();
    if (t == 0) {
        float ts = 0.f, tss = 0.f;
        #pragma unroll
        for (int w = 0; w < 16; w++) { ts += rs[w]; tss += rss[w]; }
        float mu = ts * (1.f / 32768.f);
        float var = tss * (1.f / 32768.f) - mu * mu;
        smu = mu;
        srstd = rsqrtf(var + 1e-5f);
    }
    __syncthreads();
    const float mu = smu, rstd = srstd;
    float4* o4 = (float4*)op;
    for (int i = t; i < 8192; i += 512) {
        int ch = g * 16 + (i >> 9);
        float ga = gamma[ch] * rstd;
        float be = beta[ch];
        float4 v = z4[i];
        v.x = (v.x - mu) * ga + be;
        v.y = (v.y - mu) * ga + be;
        v.z = (v.z - mu) * ga + be;
        v.w = (v.w - mu) * ga + be;
        o4[i] = v;
    }
}

// ---------------------------------------------------------------------------
extern "C" void kernel_launch(void* const* d_in, const int* in_sizes, int n_in,
                              void* d_out, int out_size)
{
    const float* x     = (const float*)d_in[0];
    const float* Wqkv  = (const float*)d_in[1];
    const float* bqkv  = (const float*)d_in[2];
    const float* Wproj = (const float*)d_in[3];
    const float* bproj = (const float*)d_in[4];
    const float* gamma = (const float*)d_in[5];
    const float* beta  = (const float*)d_in[6];
    float* out = (float*)d_out;

    float *qkv, *att, *zbuf;
    cudaGetSymbolAddress((void**)&qkv,  g_qkv);
    cudaGetSymbolAddress((void**)&att,  g_att);
    cudaGetSymbolAddress((void**)&zbuf, g_z);

    const int CL = C_DIM * L_DIM;
    const int ATTN_SMEM = (64 * 128 + 64 * 64 + 64 * 128) * 4; // 80KB
    cudaFuncSetAttribute(attn_kernel, cudaFuncAttributeMaxDynamicSharedMemorySize, ATTN_SMEM);

    // qkv = Wqkv @ x + bqkv, clipped to [-10,10]
    sgemm_kernel<true, false><<<dim3(16, 12, BATCH), 256>>>(
        Wqkv, x, qkv, bqkv, nullptr, 3 * C_DIM, L_DIM, C_DIM, CL, 3 * CL);

    // attention
    attn_kernel<<<dim3(32, HEADS, BATCH), 256, ATTN_SMEM>>>(qkv, att);

    // z = Wproj @ att + bproj + x
    sgemm_kernel<false, true><<<dim3(16, 4, BATCH), 256>>>(
        Wproj, att, zbuf, bproj, x, C_DIM, L_DIM, C_DIM, CL, CL);

    // out = groupnorm(z)
    gn_kernel<<<dim3(BATCH * 32), 512>>>(zbuf, gamma, beta, out);
}

// round 6
// speedup vs baseline: 1.8781x; 1.8781x over previous
#include <cuda_runtime.h>
#include <cuda_bf16.h>
#include <cstdint>

#define C_DIM 512
#define L_DIM 2048
#define BATCH 4
#define HEADS 8
#define HDIM 64

// ---------------------------------------------------------------------------
// Helpers
// ---------------------------------------------------------------------------
__device__ __forceinline__ uint32_t s2u(const void* p) {
    uint32_t a;
    asm("{ .reg .u64 t; cvta.to.shared.u64 t, %1; cvt.u32.u64 %0, t; }" : "=r"(a) : "l"(p));
    return a;
}
__device__ __forceinline__ void ldsm4(uint32_t* r, uint32_t a) {
    asm volatile("ldmatrix.sync.aligned.m8n8.x4.shared.b16 {%0,%1,%2,%3}, [%4];"
                 : "=r"(r[0]), "=r"(r[1]), "=r"(r[2]), "=r"(r[3]) : "r"(a));
}
__device__ __forceinline__ void mma16816(float* c, const uint32_t* a, const uint32_t* b) {
    asm volatile("mma.sync.aligned.m16n8k16.row.col.f32.bf16.bf16.f32 "
                 "{%0,%1,%2,%3}, {%4,%5,%6,%7}, {%8,%9}, {%0,%1,%2,%3};"
                 : "+f"(c[0]), "+f"(c[1]), "+f"(c[2]), "+f"(c[3])
                 : "r"(a[0]), "r"(a[1]), "r"(a[2]), "r"(a[3]), "r"(b[0]), "r"(b[1]));
}
#define SW(x) ((x) ^ (((x) >> 3) & 0x70))
__device__ __forceinline__ void split_bf(float x, __nv_bfloat16& h, __nv_bfloat16& l) {
    h = __float2bfloat16(x);
    l = __float2bfloat16(x - __bfloat162float(h));
}
__device__ __forceinline__ uint32_t packb(__nv_bfloat16 a, __nv_bfloat16 b) {
    __nv_bfloat162 t(a, b);
    return *(uint32_t*)&t;
}
// exp2 via FFMA/ALU only (no MUFU). |y| <= 14.5 guaranteed by clip.
__device__ __forceinline__ float exp2_poly(float y) {
    float r = y + 12582912.f;
    int n = __float_as_int(r) - 0x4B400000;
    float f = y - (r - 12582912.f);
    float p = 0.0013333558f;
    p = p * f + 0.0096181291f;
    p = p * f + 0.0555041087f;
    p = p * f + 0.2402265069f;
    p = p * f + 0.6931471825f;
    p = p * f + 1.0f;
    return __int_as_float(__float_as_int(p) + (n << 23));
}

// Scratch
__device__ float g_qkv[BATCH * 3 * C_DIM * L_DIM];
__device__ float g_att[BATCH * C_DIM * L_DIM];
__device__ float g_z[BATCH * C_DIM * L_DIM];

// ---------------------------------------------------------------------------
// Scalar SGEMM (R2 version, proven)
// ---------------------------------------------------------------------------
template<bool CLIP, bool RES>
__global__ __launch_bounds__(256, 2) void sgemm_kernel(
    const float* __restrict__ A, const float* __restrict__ B, float* __restrict__ Cmat,
    const float* __restrict__ bias, const float* __restrict__ res,
    int M, int N, int K, int strideB, int strideC)
{
    __shared__ float As[8][128];
    __shared__ float Bs[8][128];
    const int t = threadIdx.x;
    const int tx = t & 15, ty = t >> 4;
    const int n0 = blockIdx.x * 128, m0 = blockIdx.y * 128;
    const float* Bp = B + (size_t)blockIdx.z * strideB;
    float* Cp = Cmat + (size_t)blockIdx.z * strideC;
    const float* Rp = RES ? (res + (size_t)blockIdx.z * strideB) : nullptr;

    const int arow = t >> 1, acol = (t & 1) * 4;
    const int brow = t >> 5, bcol = (t & 31) * 4;
    const float* Aptr = A + (size_t)(m0 + arow) * K + acol;
    const float* Bptr = Bp + (size_t)brow * N + n0 + bcol;

    float acc[8][8] = {};
    for (int k0 = 0; k0 < K; k0 += 8) {
        float4 av = *(const float4*)(Aptr + k0);
        float4 bv = *(const float4*)(Bptr + (size_t)k0 * N);
        As[acol + 0][arow] = av.x;
        As[acol + 1][arow] = av.y;
        As[acol + 2][arow] = av.z;
        As[acol + 3][arow] = av.w;
        *(float4*)&Bs[brow][bcol] = bv;
        __syncthreads();
        #pragma unroll
        for (int kk = 0; kk < 8; kk++) {
            float a[8], b[8];
            *(float4*)&a[0] = *(float4*)&As[kk][ty * 4];
            *(float4*)&a[4] = *(float4*)&As[kk][64 + ty * 4];
            *(float4*)&b[0] = *(float4*)&Bs[kk][tx * 4];
            *(float4*)&b[4] = *(float4*)&Bs[kk][64 + tx * 4];
            #pragma unroll
            for (int r = 0; r < 8; r++)
                #pragma unroll
                for (int c = 0; c < 8; c++)
                    acc[r][c] += a[r] * b[c];
        }
        __syncthreads();
    }

    #pragma unroll
    for (int r = 0; r < 8; r++) {
        int m = m0 + (r >> 2) * 64 + ty * 4 + (r & 3);
        float bvl = bias[m];
        #pragma unroll
        for (int ch = 0; ch < 2; ch++) {
            int n = n0 + ch * 64 + tx * 4;
            float4 o;
            o.x = acc[r][ch * 4 + 0] + bvl;
            o.y = acc[r][ch * 4 + 1] + bvl;
            o.z = acc[r][ch * 4 + 2] + bvl;
            o.w = acc[r][ch * 4 + 3] + bvl;
            if (CLIP) {
                o.x = fminf(10.f, fmaxf(-10.f, o.x));
                o.y = fminf(10.f, fmaxf(-10.f, o.y));
                o.z = fminf(10.f, fmaxf(-10.f, o.z));
                o.w = fminf(10.f, fmaxf(-10.f, o.w));
            }
            if (RES) {
                float4 rv = *(const float4*)(Rp + (size_t)m * N + n);
                o.x += rv.x; o.y += rv.y; o.z += rv.z; o.w += rv.w;
            }
            *(float4*)(Cp + (size_t)m * N + n) = o;
        }
    }
}

// ---------------------------------------------------------------------------
// Flash attention on mma.sync bf16 (hi/lo split, 3-term).
// CTA = 128 queries of one (b,h), 8 warps; warp owns 16 query rows.
// smem: Qhi/Qlo [128][64]bf16, Khi/Klo [64j][64d], Vhi/Vlo [64d][64j]. 64KB.
// ---------------------------------------------------------------------------
#define AQHI 0
#define AQLO 16384
#define AKHI 32768
#define AKLO 40960
#define AVHI 49152
#define AVLO 57344
#define ATTN_SMEM 65536

__global__ __launch_bounds__(256) void attn_mma_kernel(
    const float* __restrict__ qkv, float* __restrict__ outp)
{
    extern __shared__ char sm[];
    const uint32_t sb = s2u(sm);
    const int tid = threadIdx.x;
    const int w = tid >> 5, lane = tid & 31;
    const int b = blockIdx.z, h = blockIdx.y;
    const int i0 = blockIdx.x * 128;
    const float* qp = qkv + ((size_t)(b * 3 * C_DIM) + h * HDIM) * L_DIM;
    const float* kp = qp + (size_t)C_DIM * L_DIM;
    const float* vp = qp + (size_t)2 * C_DIM * L_DIM;

    // ---- Q transpose + split: smem Q[i][d] (128B bf16 rows, SW swizzle)
    {
        const int dq = tid >> 2;
        const int ii0 = (tid & 3) * 32;
        const float* qr = qp + (size_t)dq * L_DIM + i0;
        #pragma unroll
        for (int u = 0; u < 8; u++) {
            float4 v = *(const float4*)(qr + ii0 + 4 * u);
            float vv[4] = {v.x, v.y, v.z, v.w};
            #pragma unroll
            for (int e = 0; e < 4; e++) {
                int i = ii0 + 4 * u + e;
                __nv_bfloat16 hb, lb; split_bf(vv[e], hb, lb);
                int off = SW(i * 128 + dq * 2);
                *(__nv_bfloat16*)(sm + AQHI + off) = hb;
                *(__nv_bfloat16*)(sm + AQLO + off) = lb;
            }
        }
    }
    __syncthreads();

    // ---- Q a-fragments (persistent): 4 k-tiles (d), hi+lo
    uint32_t qh[4][4], ql[4][4];
    {
        const int row = w * 16 + (lane & 15);
        const int colb = (lane >> 4) * 16;
        #pragma unroll
        for (int kt = 0; kt < 4; kt++) {
            uint32_t off = SW(row * 128 + kt * 32 + colb);
            ldsm4(qh[kt], sb + AQHI + off);
            ldsm4(ql[kt], sb + AQLO + off);
        }
    }

    // b-fragment lane addressing (K and V share the pattern)
    const int brow = (lane & 7) + ((lane >> 4) << 3);   // row within 16-block
    const int bcol = ((lane >> 3) & 1) * 16;            // byte offset (k halves)

    const float K1 = 0.125f * 1.44269504f;   // scale * log2(e)
    const float LIM = 10.0f * 1.44269504f;

    float oc[8][4] = {};
    float racc0 = 0.f, racc1 = 0.f;

    const int dk = tid >> 2;            // loader: d row 0..63
    const int jj0 = (tid & 3) * 16;

    for (int t = 0; t < 32; t++) {
        const int j0 = t * 64;
        __syncthreads();   // previous iteration's ldsm reads done

        // K tile transposed+split: K[j][d]
        {
            const float* kr = kp + (size_t)dk * L_DIM + j0;
            #pragma unroll
            for (int u = 0; u < 4; u++) {
                float4 v = *(const float4*)(kr + jj0 + 4 * u);
                float vv[4] = {v.x, v.y, v.z, v.w};
                #pragma unroll
                for (int e = 0; e < 4; e++) {
                    int j = jj0 + 4 * u + e;
                    __nv_bfloat16 hb, lb; split_bf(vv[e], hb, lb);
                    int off = SW(j * 128 + dk * 2);
                    *(__nv_bfloat16*)(sm + AKHI + off) = hb;
                    *(__nv_bfloat16*)(sm + AKLO + off) = lb;
                }
            }
        }
        // V tile split (native [d][j])
        {
            const float* vr = vp + (size_t)dk * L_DIM + j0;
            #pragma unroll
            for (int u = 0; u < 4; u++) {
                float4 v = *(const float4*)(vr + jj0 + 4 * u);
                __nv_bfloat16 h0, l0, h1, l1, h2, l2, h3, l3;
                split_bf(v.x, h0, l0); split_bf(v.y, h1, l1);
                split_bf(v.z, h2, l2); split_bf(v.w, h3, l3);
                int jj = jj0 + 4 * u;
                int off = SW(dk * 128 + jj * 2);
                uint2 wh = { packb(h0, h1), packb(h2, h3) };
                uint2 wl = { packb(l0, l1), packb(l2, l3) };
                *(uint2*)(sm + AVHI + off) = wh;
                *(uint2*)(sm + AVLO + off) = wl;
            }
        }
        __syncthreads();

        // ---- S = Q K^T (3-term bf16 split)
        float sc[8][4] = {};
        #pragma unroll
        for (int dt = 0; dt < 4; dt++) {
            #pragma unroll
            for (int jb = 0; jb < 4; jb++) {
                uint32_t kh[4], kl[4];
                uint32_t off = SW((jb * 16 + brow) * 128 + dt * 32 + bcol);
                ldsm4(kh, sb + AKHI + off);
                ldsm4(kl, sb + AKLO + off);
                mma16816(sc[2 * jb],     qh[dt], kh);
                mma16816(sc[2 * jb + 1], qh[dt], kh + 2);
                mma16816(sc[2 * jb],     qh[dt], kl);
                mma16816(sc[2 * jb + 1], qh[dt], kl + 2);
                mma16816(sc[2 * jb],     ql[dt], kh);
                mma16816(sc[2 * jb + 1], ql[dt], kh + 2);
            }
        }

        // ---- softmax numerator (scale, clip, exp2) + row-sum partials
        #pragma unroll
        for (int nt = 0; nt < 8; nt++) {
            #pragma unroll
            for (int k = 0; k < 4; k++) {
                float y = sc[nt][k] * K1;
                y = fminf(LIM, fmaxf(-LIM, y));
                float p = exp2_poly(y);
                sc[nt][k] = p;
                if (k < 2) racc0 += p; else racc1 += p;
            }
        }

        // ---- pack P into a-fragments (hi/lo) straight from registers
        uint32_t ph[4][4], pl[4][4];
        #pragma unroll
        for (int q = 0; q < 4; q++) {
            __nv_bfloat16 h0, l0, h1, l1;
            split_bf(sc[2 * q][0], h0, l0); split_bf(sc[2 * q][1], h1, l1);
            ph[q][0] = packb(h0, h1); pl[q][0] = packb(l0, l1);
            split_bf(sc[2 * q][2], h0, l0); split_bf(sc[2 * q][3], h1, l1);
            ph[q][1] = packb(h0, h1); pl[q][1] = packb(l0, l1);
            split_bf(sc[2 * q + 1][0], h0, l0); split_bf(sc[2 * q + 1][1], h1, l1);
            ph[q][2] = packb(h0, h1); pl[q][2] = packb(l0, l1);
            split_bf(sc[2 * q + 1][2], h0, l0); split_bf(sc[2 * q + 1][3], h1, l1);
            ph[q][3] = packb(h0, h1); pl[q][3] = packb(l0, l1);
        }

        // ---- O += P V^T (3-term bf16 split)
        #pragma unroll
        for (int kt = 0; kt < 4; kt++) {
            #pragma unroll
            for (int db = 0; db < 4; db++) {
                uint32_t vh[4], vl[4];
                uint32_t off = SW((db * 16 + brow) * 128 + kt * 32 + bcol);
                ldsm4(vh, sb + AVHI + off);
                ldsm4(vl, sb + AVLO + off);
                mma16816(oc[2 * db],     ph[kt], vh);
                mma16816(oc[2 * db + 1], ph[kt], vh + 2);
                mma16816(oc[2 * db],     ph[kt], vl);
                mma16816(oc[2 * db + 1], ph[kt], vl + 2);
                mma16816(oc[2 * db],     pl[kt], vh);
                mma16816(oc[2 * db + 1], pl[kt], vh + 2);
            }
        }
    }

    // ---- row denominators (quad reduce) and write-out
    racc0 += __shfl_xor_sync(0xffffffffu, racc0, 1);
    racc0 += __shfl_xor_sync(0xffffffffu, racc0, 2);
    racc1 += __shfl_xor_sync(0xffffffffu, racc1, 1);
    racc1 += __shfl_xor_sync(0xffffffffu, racc1, 2);
    const float inv0 = 1.0f / racc0;
    const float inv1 = 1.0f / racc1;

    float* ob = outp + ((size_t)(b * C_DIM) + h * HDIM) * L_DIM;
    const int ibase = i0 + w * 16 + (lane >> 2);
    #pragma unroll
    for (int nt = 0; nt < 8; nt++) {
        int d = nt * 8 + 2 * (lane & 3);
        ob[(size_t)d * L_DIM + ibase]           = oc[nt][0] * inv0;
        ob[(size_t)(d + 1) * L_DIM + ibase]     = oc[nt][1] * inv0;
        ob[(size_t)d * L_DIM + ibase + 8]       = oc[nt][2] * inv1;
        ob[(size_t)(d + 1) * L_DIM + ibase + 8] = oc[nt][3] * inv1;
    }
}

// ---------------------------------------------------------------------------
// GroupNorm (R2 version)
// ---------------------------------------------------------------------------
__global__ __launch_bounds__(256) void gn_kernel(
    const float* __restrict__ z, const float* __restrict__ gamma,
    const float* __restrict__ beta, float* __restrict__ outp)
{
    const int bg = blockIdx.x;
    const int b = bg >> 5, g = bg & 31;
    const float* zp = z + ((size_t)b * C_DIM + g * 16) * L_DIM;
    float* op = outp + ((size_t)b * C_DIM + g * 16) * L_DIM;
    const int t = threadIdx.x;

    float s = 0.f, ss = 0.f;
    const float4* z4 = (const float4*)zp;
    for (int i = t; i < 8192; i += 256) {
        float4 v = z4[i];
        s  += v.x + v.y + v.z + v.w;
        ss += v.x * v.x + v.y * v.y + v.z * v.z + v.w * v.w;
    }
    __shared__ float rs[8], rss[8];
    __shared__ float smu, srstd;
    #pragma unroll
    for (int o = 16; o; o >>= 1) {
        s  += __shfl_xor_sync(0xffffffffu, s, o);
        ss += __shfl_xor_sync(0xffffffffu, ss, o);
    }
    if ((t & 31) == 0) { rs[t >> 5] = s; rss[t >> 5] = ss; }
    __syncthreads();
    if (t == 0) {
        float ts = 0.f, tss = 0.f;
        #pragma unroll
        for (int wv = 0; wv < 8; wv++) { ts += rs[wv]; tss += rss[wv]; }
        float mu = ts * (1.f / 32768.f);
        float var = tss * (1.f / 32768.f) - mu * mu;
        smu = mu;
        srstd = rsqrtf(var + 1e-5f);
    }
    __syncthreads();
    const float mu = smu, rstd = srstd;
    float4* o4 = (float4*)op;
    for (int i = t; i < 8192; i += 256) {
        int ch = g * 16 + (i >> 9);
        float ga = gamma[ch] * rstd;
        float be = beta[ch];
        float4 v = z4[i];
        v.x = (v.x - mu) * ga + be;
        v.y = (v.y - mu) * ga + be;
        v.z = (v.z - mu) * ga + be;
        v.w = (v.w - mu) * ga + be;
        o4[i] = v;
    }
}

// ---------------------------------------------------------------------------
extern "C" void kernel_launch(void* const* d_in, const int* in_sizes, int n_in,
                              void* d_out, int out_size)
{
    const float* x     = (const float*)d_in[0];
    const float* Wqkv  = (const float*)d_in[1];
    const float* bqkv  = (const float*)d_in[2];
    const float* Wproj = (const float*)d_in[3];
    const float* bproj = (const float*)d_in[4];
    const float* gamma = (const float*)d_in[5];
    const float* beta  = (const float*)d_in[6];
    float* out = (float*)d_out;

    float *qkv, *att, *zbuf;
    cudaGetSymbolAddress((void**)&qkv,  g_qkv);
    cudaGetSymbolAddress((void**)&att,  g_att);
    cudaGetSymbolAddress((void**)&zbuf, g_z);

    const int CL = C_DIM * L_DIM;
    cudaFuncSetAttribute(attn_mma_kernel, cudaFuncAttributeMaxDynamicSharedMemorySize, ATTN_SMEM);

    // qkv = Wqkv @ x + bqkv, clipped to [-10,10]
    sgemm_kernel<true, false><<<dim3(16, 12, BATCH), 256>>>(
        Wqkv, x, qkv, bqkv, nullptr, 3 * C_DIM, L_DIM, C_DIM, CL, 3 * CL);

    // attention (mma.sync bf16 tensor cores)
    attn_mma_kernel<<<dim3(16, HEADS, BATCH), 256, ATTN_SMEM>>>(qkv, att);

    // z = Wproj @ att + bproj + x
    sgemm_kernel<false, true><<<dim3(16, 4, BATCH), 256>>>(
        Wproj, att, zbuf, bproj, x, C_DIM, L_DIM, C_DIM, CL, CL);

    // out = groupnorm(z)
    gn_kernel<<<dim3(BATCH * 32), 256>>>(zbuf, gamma, beta, out);
}

// round 10
// speedup vs baseline: 2.0624x; 1.0981x over previous
#include <cuda_runtime.h>
#include <cuda_bf16.h>
#include <cstdint>

#define C_DIM 512
#define L_DIM 2048
#define BATCH 4
#define HEADS 8
#define HDIM 64

// ---------------------------------------------------------------------------
// Helpers
// ---------------------------------------------------------------------------
__device__ __forceinline__ uint32_t s2u(const void* p) {
    uint32_t a;
    asm("{ .reg .u64 t; cvta.to.shared.u64 t, %1; cvt.u32.u64 %0, t; }" : "=r"(a) : "l"(p));
    return a;
}
__device__ __forceinline__ void ldsm4(uint32_t* r, uint32_t a) {
    asm volatile("ldmatrix.sync.aligned.m8n8.x4.shared.b16 {%0,%1,%2,%3}, [%4];"
                 : "=r"(r[0]), "=r"(r[1]), "=r"(r[2]), "=r"(r[3]) : "r"(a));
}
__device__ __forceinline__ void mma16816(float* c, const uint32_t* a, const uint32_t* b) {
    asm volatile("mma.sync.aligned.m16n8k16.row.col.f32.bf16.bf16.f32 "
                 "{%0,%1,%2,%3}, {%4,%5,%6,%7}, {%8,%9}, {%0,%1,%2,%3};"
                 : "+f"(c[0]), "+f"(c[1]), "+f"(c[2]), "+f"(c[3])
                 : "r"(a[0]), "r"(a[1]), "r"(a[2]), "r"(a[3]), "r"(b[0]), "r"(b[1]));
}
#define SW(x)  ((x) ^ (((x) >> 3) & 0x70))   // 128B-row swizzle
#define GSW(x) ((x) ^ (((x) >> 3) & 0x30))   // 64B-row swizzle
__device__ __forceinline__ void split_bf(float x, __nv_bfloat16& h, __nv_bfloat16& l) {
    h = __float2bfloat16(x);
    l = __float2bfloat16(x - __bfloat162float(h));
}
__device__ __forceinline__ uint32_t packb(__nv_bfloat16 a, __nv_bfloat16 b) {
    __nv_bfloat162 t(a, b);
    return *(uint32_t*)&t;
}
// exp2 via FFMA/ALU only (no MUFU). |y| <= 14.5 guaranteed by clip.
__device__ __forceinline__ float exp2_poly(float y) {
    float r = y + 12582912.f;
    int n = __float_as_int(r) - 0x4B400000;
    float f = y - (r - 12582912.f);
    float p = 0.0013333558f;
    p = p * f + 0.0096181291f;
    p = p * f + 0.0555041087f;
    p = p * f + 0.2402265069f;
    p = p * f + 0.6931471825f;
    p = p * f + 1.0f;
    return __int_as_float(__float_as_int(p) + (n << 23));
}

// Scratch
__device__ float g_qkv[BATCH * 3 * C_DIM * L_DIM];
__device__ float g_att[BATCH * C_DIM * L_DIM];
__device__ float g_z[BATCH * C_DIM * L_DIM];

// ---------------------------------------------------------------------------
// Tensor-core GEMM: C[b] = A[MxK] * B[b][KxN] + bias (optional clip / +res)
// bf16 hi/lo split, 3-term. BM=BN=128, BK=32, 256 threads, warp grid 4x2.
// smem tiles: A[m][k] 64B rows, B transposed [n][k] 64B rows, SW64 swizzle.
// ---------------------------------------------------------------------------
template<bool CLIP, bool RES>
__global__ __launch_bounds__(256, 2) void mma_gemm_kernel(
    const float* __restrict__ A, const float* __restrict__ B, float* __restrict__ Cmat,
    const float* __restrict__ bias, const float* __restrict__ res,
    int M, int N, int K, int strideB, int strideC)
{
    __shared__ __nv_bfloat16 AHI[128 * 32], ALO[128 * 32];
    __shared__ __nv_bfloat16 BHI[128 * 32], BLO[128 * 32];
    const uint32_t sAH = s2u(AHI), sAL = s2u(ALO);
    const uint32_t sBH = s2u(BHI), sBL = s2u(BLO);

    const int t = threadIdx.x;
    const int warp = t >> 5, lane = t & 31;
    const int wm = warp & 3, wn = warp >> 2;
    const int m0w = wm * 32, n0w = wn * 64;
    const int n0 = blockIdx.x * 128, m0 = blockIdx.y * 128;
    const float* Bp = B + (size_t)blockIdx.z * strideB;
    float* Cp = Cmat + (size_t)blockIdx.z * strideC;
    const float* Rp = RES ? (res + (size_t)blockIdx.z * strideB) : nullptr;

    // loader mapping
    const int ar = t >> 1, ac0 = (t & 1) * 16;          // A: row, 16 k each
    const int bk = t >> 3, bn0 = (t & 7) * 16;          // B: k row, 16 n each
    const float* Ap = A + (size_t)(m0 + ar) * K + ac0;
    const float* Bpt = Bp + n0 + bn0;

    // b-fragment lane addressing
    const int brow = (lane & 7) + ((lane >> 4) << 3);
    const int bcol = ((lane >> 3) & 1) * 16;

    float acc[2][8][4] = {};

    for (int k0 = 0; k0 < K; k0 += 32) {
        // ---- A tile: [m][k], split hi/lo
        {
            const float* ap = Ap + k0;
            #pragma unroll
            for (int u = 0; u < 4; u++) {
                float4 v = *(const float4*)(ap + 4 * u);
                __nv_bfloat16 h0, l0, h1, l1, h2, l2, h3, l3;
                split_bf(v.x, h0, l0); split_bf(v.y, h1, l1);
                split_bf(v.z, h2, l2); split_bf(v.w, h3, l3);
                int c = ac0 + 4 * u;
                uint32_t o0 = GSW(ar * 64 + c * 2);
                uint32_t o1 = GSW(ar * 64 + (c + 2) * 2);
                *(uint32_t*)((char*)AHI + o0) = packb(h0, h1);
                *(uint32_t*)((char*)AHI + o1) = packb(h2, h3);
                *(uint32_t*)((char*)ALO + o0) = packb(l0, l1);
                *(uint32_t*)((char*)ALO + o1) = packb(l2, l3);
            }
        }
        // ---- B tile: transpose to [n][k], split hi/lo
        {
            const float* bp = Bpt + (size_t)(k0 + bk) * N;
            #pragma unroll
            for (int u = 0; u < 4; u++) {
                float4 v = *(const float4*)(bp + 4 * u);
                float vv[4] = {v.x, v.y, v.z, v.w};
                #pragma unroll
                for (int e = 0; e < 4; e++) {
                    int n = bn0 + 4 * u + e;
                    __nv_bfloat16 hb, lb; split_bf(vv[e], hb, lb);
                    uint32_t off = GSW(n * 64 + bk * 2);
                    *(__nv_bfloat16*)((char*)BHI + off) = hb;
                    *(__nv_bfloat16*)((char*)BLO + off) = lb;
                }
            }
        }
        __syncthreads();

        #pragma unroll
        for (int kt = 0; kt < 2; kt++) {
            uint32_t ah[2][4], al[2][4];
            #pragma unroll
            for (int mi = 0; mi < 2; mi++) {
                uint32_t off = GSW((m0w + mi * 16 + (lane & 15)) * 64 + kt * 32 + (lane >> 4) * 16);
                ldsm4(ah[mi], sAH + off);
                ldsm4(al[mi], sAL + off);
            }
            #pragma unroll
            for (int nb = 0; nb < 4; nb++) {
                uint32_t bh[4], bl[4];
                uint32_t off = GSW((n0w + nb * 16 + brow) * 64 + kt * 32 + bcol);
                ldsm4(bh, sBH + off);
                ldsm4(bl, sBL + off);
                #pragma unroll
                for (int mi = 0; mi < 2; mi++) {
                    mma16816(acc[mi][2 * nb],     ah[mi], bh);
                    mma16816(acc[mi][2 * nb + 1], ah[mi], bh + 2);
                    mma16816(acc[mi][2 * nb],     ah[mi], bl);
                    mma16816(acc[mi][2 * nb + 1], ah[mi], bl + 2);
                    mma16816(acc[mi][2 * nb],     al[mi], bh);
                    mma16816(acc[mi][2 * nb + 1], al[mi], bh + 2);
                }
            }
        }
        __syncthreads();
    }

    // ---- epilogue
    #pragma unroll
    for (int mi = 0; mi < 2; mi++) {
        int r0 = m0 + m0w + mi * 16 + (lane >> 2);
        float b0 = bias[r0], b1 = bias[r0 + 8];
        #pragma unroll
        for (int nb = 0; nb < 8; nb++) {
            int col = n0 + n0w + nb * 8 + (lane & 3) * 2;
            float2 v0 = { acc[mi][nb][0] + b0, acc[mi][nb][1] + b0 };
            float2 v1 = { acc[mi][nb][2] + b1, acc[mi][nb][3] + b1 };
            if (CLIP) {
                v0.x = fminf(10.f, fmaxf(-10.f, v0.x));
                v0.y = fminf(10.f, fmaxf(-10.f, v0.y));
                v1.x = fminf(10.f, fmaxf(-10.f, v1.x));
                v1.y = fminf(10.f, fmaxf(-10.f, v1.y));
            }
            if (RES) {
                float2 r0v = *(const float2*)(Rp + (size_t)r0 * N + col);
                float2 r1v = *(const float2*)(Rp + (size_t)(r0 + 8) * N + col);
                v0.x += r0v.x; v0.y += r0v.y;
                v1.x += r1v.x; v1.y += r1v.y;
            }
            *(float2*)(Cp + (size_t)r0 * N + col) = v0;
            *(float2*)(Cp + (size_t)(r0 + 8) * N + col) = v1;
        }
    }
}

// ---------------------------------------------------------------------------
// Flash attention on mma.sync bf16 (hi/lo split, 3-term). (R6, proven)
// ---------------------------------------------------------------------------
#define AQHI 0
#define AQLO 16384
#define AKHI 32768
#define AKLO 40960
#define AVHI 49152
#define AVLO 57344
#define ATTN_SMEM 65536

__global__ __launch_bounds__(256) void attn_mma_kernel(
    const float* __restrict__ qkv, float* __restrict__ outp)
{
    extern __shared__ char sm[];
    const uint32_t sb = s2u(sm);
    const int tid = threadIdx.x;
    const int w = tid >> 5, lane = tid & 31;
    const int b = blockIdx.z, h = blockIdx.y;
    const int i0 = blockIdx.x * 128;
    const float* qp = qkv + ((size_t)(b * 3 * C_DIM) + h * HDIM) * L_DIM;
    const float* kp = qp + (size_t)C_DIM * L_DIM;
    const float* vp = qp + (size_t)2 * C_DIM * L_DIM;

    {
        const int dq = tid >> 2;
        const int ii0 = (tid & 3) * 32;
        const float* qr = qp + (size_t)dq * L_DIM + i0;
        #pragma unroll
        for (int u = 0; u < 8; u++) {
            float4 v = *(const float4*)(qr + ii0 + 4 * u);
            float vv[4] = {v.x, v.y, v.z, v.w};
            #pragma unroll
            for (int e = 0; e < 4; e++) {
                int i = ii0 + 4 * u + e;
                __nv_bfloat16 hb, lb; split_bf(vv[e], hb, lb);
                int off = SW(i * 128 + dq * 2);
                *(__nv_bfloat16*)(sm + AQHI + off) = hb;
                *(__nv_bfloat16*)(sm + AQLO + off) = lb;
            }
        }
    }
    __syncthreads();

    uint32_t qh[4][4], ql[4][4];
    {
        const int row = w * 16 + (lane & 15);
        const int colb = (lane >> 4) * 16;
        #pragma unroll
        for (int kt = 0; kt < 4; kt++) {
            uint32_t off = SW(row * 128 + kt * 32 + colb);
            ldsm4(qh[kt], sb + AQHI + off);
            ldsm4(ql[kt], sb + AQLO + off);
        }
    }

    const int brow = (lane & 7) + ((lane >> 4) << 3);
    const int bcol = ((lane >> 3) & 1) * 16;

    const float K1 = 0.125f * 1.44269504f;
    const float LIM = 10.0f * 1.44269504f;

    float oc[8][4] = {};
    float racc0 = 0.f, racc1 = 0.f;

    const int dk = tid >> 2;
    const int jj0 = (tid & 3) * 16;

    for (int t = 0; t < 32; t++) {
        const int j0 = t * 64;
        __syncthreads();

        {
            const float* kr = kp + (size_t)dk * L_DIM + j0;
            #pragma unroll
            for (int u = 0; u < 4; u++) {
                float4 v = *(const float4*)(kr + jj0 + 4 * u);
                float vv[4] = {v.x, v.y, v.z, v.w};
                #pragma unroll
                for (int e = 0; e < 4; e++) {
                    int j = jj0 + 4 * u + e;
                    __nv_bfloat16 hb, lb; split_bf(vv[e], hb, lb);
                    int off = SW(j * 128 + dk * 2);
                    *(__nv_bfloat16*)(sm + AKHI + off) = hb;
                    *(__nv_bfloat16*)(sm + AKLO + off) = lb;
                }
            }
        }
        {
            const float* vr = vp + (size_t)dk * L_DIM + j0;
            #pragma unroll
            for (int u = 0; u < 4; u++) {
                float4 v = *(const float4*)(vr + jj0 + 4 * u);
                __nv_bfloat16 h0, l0, h1, l1, h2, l2, h3, l3;
                split_bf(v.x, h0, l0); split_bf(v.y, h1, l1);
                split_bf(v.z, h2, l2); split_bf(v.w, h3, l3);
                int jj = jj0 + 4 * u;
                int off = SW(dk * 128 + jj * 2);
                uint2 wh = { packb(h0, h1), packb(h2, h3) };
                uint2 wl = { packb(l0, l1), packb(l2, l3) };
                *(uint2*)(sm + AVHI + off) = wh;
                *(uint2*)(sm + AVLO + off) = wl;
            }
        }
        __syncthreads();

        float sc[8][4] = {};
        #pragma unroll
        for (int dt = 0; dt < 4; dt++) {
            #pragma unroll
            for (int jb = 0; jb < 4; jb++) {
                uint32_t kh[4], kl[4];
                uint32_t off = SW((jb * 16 + brow) * 128 + dt * 32 + bcol);
                ldsm4(kh, sb + AKHI + off);
                ldsm4(kl, sb + AKLO + off);
                mma16816(sc[2 * jb],     qh[dt], kh);
                mma16816(sc[2 * jb + 1], qh[dt], kh + 2);
                mma16816(sc[2 * jb],     qh[dt], kl);
                mma16816(sc[2 * jb + 1], qh[dt], kl + 2);
                mma16816(sc[2 * jb],     ql[dt], kh);
                mma16816(sc[2 * jb + 1], ql[dt], kh + 2);
            }
        }

        #pragma unroll
        for (int nt = 0; nt < 8; nt++) {
            #pragma unroll
            for (int k = 0; k < 4; k++) {
                float y = sc[nt][k] * K1;
                y = fminf(LIM, fmaxf(-LIM, y));
                float p = exp2_poly(y);
                sc[nt][k] = p;
                if (k < 2) racc0 += p; else racc1 += p;
            }
        }

        uint32_t ph[4][4], pl[4][4];
        #pragma unroll
        for (int q = 0; q < 4; q++) {
            __nv_bfloat16 h0, l0, h1, l1;
            split_bf(sc[2 * q][0], h0, l0); split_bf(sc[2 * q][1], h1, l1);
            ph[q][0] = packb(h0, h1); pl[q][0] = packb(l0, l1);
            split_bf(sc[2 * q][2], h0, l0); split_bf(sc[2 * q][3], h1, l1);
            ph[q][1] = packb(h0, h1); pl[q][1] = packb(l0, l1);
            split_bf(sc[2 * q + 1][0], h0, l0); split_bf(sc[2 * q + 1][1], h1, l1);
            ph[q][2] = packb(h0, h1); pl[q][2] = packb(l0, l1);
            split_bf(sc[2 * q + 1][2], h0, l0); split_bf(sc[2 * q + 1][3], h1, l1);
            ph[q][3] = packb(h0, h1); pl[q][3] = packb(l0, l1);
        }

        #pragma unroll
        for (int kt = 0; kt < 4; kt++) {
            #pragma unroll
            for (int db = 0; db < 4; db++) {
                uint32_t vh[4], vl[4];
                uint32_t off = SW((db * 16 + brow) * 128 + kt * 32 + bcol);
                ldsm4(vh, sb + AVHI + off);
                ldsm4(vl, sb + AVLO + off);
                mma16816(oc[2 * db],     ph[kt], vh);
                mma16816(oc[2 * db + 1], ph[kt], vh + 2);
                mma16816(oc[2 * db],     ph[kt], vl);
                mma16816(oc[2 * db + 1], ph[kt], vl + 2);
                mma16816(oc[2 * db],     pl[kt], vh);
                mma16816(oc[2 * db + 1], pl[kt], vh + 2);
            }
        }
    }

    racc0 += __shfl_xor_sync(0xffffffffu, racc0, 1);
    racc0 += __shfl_xor_sync(0xffffffffu, racc0, 2);
    racc1 += __shfl_xor_sync(0xffffffffu, racc1, 1);
    racc1 += __shfl_xor_sync(0xffffffffu, racc1, 2);
    const float inv0 = 1.0f / racc0;
    const float inv1 = 1.0f / racc1;

    float* ob = outp + ((size_t)(b * C_DIM) + h * HDIM) * L_DIM;
    const int ibase = i0 + w * 16 + (lane >> 2);
    #pragma unroll
    for (int nt = 0; nt < 8; nt++) {
        int d = nt * 8 + 2 * (lane & 3);
        ob[(size_t)d * L_DIM + ibase]           = oc[nt][0] * inv0;
        ob[(size_t)(d + 1) * L_DIM + ibase]     = oc[nt][1] * inv0;
        ob[(size_t)d * L_DIM + ibase + 8]       = oc[nt][2] * inv1;
        ob[(size_t)(d + 1) * L_DIM + ibase + 8] = oc[nt][3] * inv1;
    }
}

// ---------------------------------------------------------------------------
// GroupNorm (proven)
// ---------------------------------------------------------------------------
__global__ __launch_bounds__(256) void gn_kernel(
    const float* __restrict__ z, const float* __restrict__ gamma,
    const float* __restrict__ beta, float* __restrict__ outp)
{
    const int bg = blockIdx.x;
    const int b = bg >> 5, g = bg & 31;
    const float* zp = z + ((size_t)b * C_DIM + g * 16) * L_DIM;
    float* op = outp + ((size_t)b * C_DIM + g * 16) * L_DIM;
    const int t = threadIdx.x;

    float s = 0.f, ss = 0.f;
    const float4* z4 = (const float4*)zp;
    for (int i = t; i < 8192; i += 256) {
        float4 v = z4[i];
        s  += v.x + v.y + v.z + v.w;
        ss += v.x * v.x + v.y * v.y + v.z * v.z + v.w * v.w;
    }
    __shared__ float rs[8], rss[8];
    __shared__ float smu, srstd;
    #pragma unroll
    for (int o = 16; o; o >>= 1) {
        s  += __shfl_xor_sync(0xffffffffu, s, o);
        ss += __shfl_xor_sync(0xffffffffu, ss, o);
    }
    if ((t & 31) == 0) { rs[t >> 5] = s; rss[t >> 5] = ss; }
    __syncthreads();
    if (t == 0) {
        float ts = 0.f, tss = 0.f;
        #pragma unroll
        for (int wv = 0; wv < 8; wv++) { ts += rs[wv]; tss += rss[wv]; }
        float mu = ts * (1.f / 32768.f);
        float var = tss * (1.f / 32768.f) - mu * mu;
        smu = mu;
        srstd = rsqrtf(var + 1e-5f);
    }
    __syncthreads();
    const float mu = smu, rstd = srstd;
    float4* o4 = (float4*)op;
    for (int i = t; i < 8192; i += 256) {
        int ch = g * 16 + (i >> 9);
        float ga = gamma[ch] * rstd;
        float be = beta[ch];
        float4 v = z4[i];
        v.x = (v.x - mu) * ga + be;
        v.y = (v.y - mu) * ga + be;
        v.z = (v.z - mu) * ga + be;
        v.w = (v.w - mu) * ga + be;
        o4[i] = v;
    }
}

// ---------------------------------------------------------------------------
extern "C" void kernel_launch(void* const* d_in, const int* in_sizes, int n_in,
                              void* d_out, int out_size)
{
    const float* x     = (const float*)d_in[0];
    const float* Wqkv  = (const float*)d_in[1];
    const float* bqkv  = (const float*)d_in[2];
    const float* Wproj = (const float*)d_in[3];
    const float* bproj = (const float*)d_in[4];
    const float* gamma = (const float*)d_in[5];
    const float* beta  = (const float*)d_in[6];
    float* out = (float*)d_out;

    float *qkv, *att, *zbuf;
    cudaGetSymbolAddress((void**)&qkv,  g_qkv);
    cudaGetSymbolAddress((void**)&att,  g_att);
    cudaGetSymbolAddress((void**)&zbuf, g_z);

    const int CL = C_DIM * L_DIM;
    cudaFuncSetAttribute(attn_mma_kernel, cudaFuncAttributeMaxDynamicSharedMemorySize, ATTN_SMEM);

    // qkv = Wqkv @ x + bqkv, clipped to [-10,10]
    mma_gemm_kernel<true, false><<<dim3(16, 12, BATCH), 256>>>(
        Wqkv, x, qkv, bqkv, nullptr, 3 * C_DIM, L_DIM, C_DIM, CL, 3 * CL);

    // attention (mma.sync bf16 tensor cores)
    attn_mma_kernel<<<dim3(16, HEADS, BATCH), 256, ATTN_SMEM>>>(qkv, att);

    // z = Wproj @ att + bproj + x
    mma_gemm_kernel<false, true><<<dim3(16, 4, BATCH), 256>>>(
        Wproj, att, zbuf, bproj, x, C_DIM, L_DIM, C_DIM, CL, CL);

    // out = groupnorm(z)
    gn_kernel<<<dim3(BATCH * 32), 256>>>(zbuf, gamma, beta, out);
}

// round 11
// speedup vs baseline: 2.6463x; 1.2831x over previous
#include <cuda_runtime.h>
#include <cuda_bf16.h>
#include <cstdint>

#define C_DIM 512
#define L_DIM 2048
#define BATCH 4
#define HEADS 8
#define HDIM 64
#define CL (C_DIM * L_DIM)

// ---------------------------------------------------------------------------
// Helpers
// ---------------------------------------------------------------------------
__device__ __forceinline__ uint32_t s2u(const void* p) {
    uint32_t a;
    asm("{ .reg .u64 t; cvta.to.shared.u64 t, %1; cvt.u32.u64 %0, t; }" : "=r"(a) : "l"(p));
    return a;
}
__device__ __forceinline__ void ldsm4(uint32_t* r, uint32_t a) {
    asm volatile("ldmatrix.sync.aligned.m8n8.x4.shared.b16 {%0,%1,%2,%3}, [%4];"
                 : "=r"(r[0]), "=r"(r[1]), "=r"(r[2]), "=r"(r[3]) : "r"(a));
}
__device__ __forceinline__ void mma16816(float* c, const uint32_t* a, const uint32_t* b) {
    asm volatile("mma.sync.aligned.m16n8k16.row.col.f32.bf16.bf16.f32 "
                 "{%0,%1,%2,%3}, {%4,%5,%6,%7}, {%8,%9}, {%0,%1,%2,%3};"
                 : "+f"(c[0]), "+f"(c[1]), "+f"(c[2]), "+f"(c[3])
                 : "r"(a[0]), "r"(a[1]), "r"(a[2]), "r"(a[3]), "r"(b[0]), "r"(b[1]));
}
#define SW(x)  ((x) ^ (((x) >> 3) & 0x70))   // 128B-row swizzle
#define GSW(x) ((x) ^ (((x) >> 3) & 0x30))   // 64B-row swizzle
__device__ __forceinline__ void split_bf(float x, __nv_bfloat16& h, __nv_bfloat16& l) {
    h = __float2bfloat16(x);
    l = __float2bfloat16(x - __bfloat162float(h));
}
__device__ __forceinline__ uint32_t packb(__nv_bfloat16 a, __nv_bfloat16 b) {
    __nv_bfloat162 t(a, b);
    return *(uint32_t*)&t;
}
// exp2 via FFMA/ALU only (no MUFU). |y| <= 14.5 guaranteed by clip.
__device__ __forceinline__ float exp2_poly(float y) {
    float r = y + 12582912.f;
    int n = __float_as_int(r) - 0x4B400000;
    float f = y - (r - 12582912.f);
    float p = 0.0013333558f;
    p = p * f + 0.0096181291f;
    p = p * f + 0.0555041087f;
    p = p * f + 0.2402265069f;
    p = p * f + 0.6931471825f;
    p = p * f + 1.0f;
    return __int_as_float(__float_as_int(p) + (n << 23));
}

// ---------------------------------------------------------------------------
// Scratch (__device__ globals; alloc-free rule)
// ---------------------------------------------------------------------------
__device__ float g_qkv[BATCH * 3 * CL];
__device__ float g_z[BATCH * CL];
__device__ __nv_bfloat16 g_xTh[BATCH * CL], g_xTl[BATCH * CL];           // x^T  [b][l][c]
__device__ __nv_bfloat16 g_qkTh[BATCH * 16 * L_DIM * HDIM], g_qkTl[BATCH * 16 * L_DIM * HDIM]; // [b][hh][l][d]
__device__ __nv_bfloat16 g_vh[BATCH * CL], g_vl[BATCH * CL];             // V native [b][c][l]
__device__ __nv_bfloat16 g_aTh[BATCH * CL], g_aTl[BATCH * CL];           // att^T [b][l][c]
__device__ __nv_bfloat16 g_wqh[3 * C_DIM * C_DIM], g_wql[3 * C_DIM * C_DIM];
__device__ __nv_bfloat16 g_wph[C_DIM * C_DIM], g_wpl[C_DIM * C_DIM];

// ---------------------------------------------------------------------------
// Elementwise fp32 -> bf16 hi/lo split
// ---------------------------------------------------------------------------
__global__ __launch_bounds__(256) void esplit_kernel(
    const float* __restrict__ s, __nv_bfloat16* __restrict__ dh,
    __nv_bfloat16* __restrict__ dl, int n4)
{
    int i = blockIdx.x * 256 + threadIdx.x;
    if (i >= n4) return;
    float4 v = ((const float4*)s)[i];
    __nv_bfloat16 h0, l0, h1, l1, h2, l2, h3, l3;
    split_bf(v.x, h0, l0); split_bf(v.y, h1, l1);
    split_bf(v.z, h2, l2); split_bf(v.w, h3, l3);
    uint2 wh = { packb(h0, h1), packb(h2, h3) };
    uint2 wl = { packb(l0, l1), packb(l2, l3) };
    ((uint2*)dh)[i] = wh;
    ((uint2*)dl)[i] = wl;
}

// ---------------------------------------------------------------------------
// Transpose + split: src fp32 [64 rows][L_DIM stride, 128 cols used]
//   -> dst hi/lo bf16 [128 l-rows][64], row stride dstStride
// ---------------------------------------------------------------------------
__device__ __forceinline__ void tsplit_tile(
    const float* src, __nv_bfloat16* dh, __nv_bfloat16* dl, int dstStride)
{
    __shared__ __nv_bfloat16 th[128 * 64], tl[128 * 64];
    const int t = threadIdx.x;
    {
        int r = t >> 2, cb = (t & 3) * 32;
        const float4* s4 = (const float4*)(src + (size_t)r * L_DIM + cb);
        #pragma unroll
        for (int u = 0; u < 8; u++) {
            float4 v = s4[u];
            float vv[4] = {v.x, v.y, v.z, v.w};
            #pragma unroll
            for (int e = 0; e < 4; e++) {
                int c = cb + 4 * u + e;
                __nv_bfloat16 hb, lb; split_bf(vv[e], hb, lb);
                th[c * 64 + r] = hb;
                tl[c * 64 + r] = lb;
            }
        }
    }
    __syncthreads();
    {
        int l = t >> 1, eo = (t & 1) * 32;
        __nv_bfloat16* dph = dh + (size_t)l * dstStride + eo;
        __nv_bfloat16* dpl = dl + (size_t)l * dstStride + eo;
        #pragma unroll
        for (int u = 0; u < 4; u++) {
            *(uint4*)(dph + 8 * u) = *(uint4*)&th[l * 64 + eo + 8 * u];
            *(uint4*)(dpl + 8 * u) = *(uint4*)&tl[l * 64 + eo + 8 * u];
        }
    }
}

__global__ __launch_bounds__(256) void tsplit_x_kernel(
    const float* __restrict__ x, __nv_bfloat16* __restrict__ dh, __nv_bfloat16* __restrict__ dl)
{
    const int lc = blockIdx.x, cc = blockIdx.y, b = blockIdx.z;
    const float* src = x + ((size_t)b * C_DIM + cc * 64) * L_DIM + lc * 128;
    size_t doff = ((size_t)b * L_DIM + lc * 128) * C_DIM + cc * 64;
    tsplit_tile(src, dh + doff, dl + doff, C_DIM);
}

__global__ __launch_bounds__(256) void tsplit_qk_kernel(
    const float* __restrict__ qkv, __nv_bfloat16* __restrict__ dh, __nv_bfloat16* __restrict__ dl)
{
    const int lc = blockIdx.x, hh = blockIdx.y, b = blockIdx.z;
    const float* src = qkv + ((size_t)b * 3 * C_DIM + hh * 64) * L_DIM + lc * 128;
    size_t doff = ((size_t)(b * 16 + hh) * L_DIM + lc * 128) * HDIM;
    tsplit_tile(src, dh + doff, dl + doff, HDIM);
}

// ---------------------------------------------------------------------------
// Tensor-core GEMM on pre-split bf16: C[b][m][n] = sum_k A[m][k]*B[b][n][k]
// BM=BN=128, BK=32, 256 threads, warp grid 4x2, register prefetch.
// ---------------------------------------------------------------------------
template<bool CLIP, bool RES>
__global__ __launch_bounds__(256) void mma_gemm_kernel(
    const __nv_bfloat16* __restrict__ Ah, const __nv_bfloat16* __restrict__ Al,
    const __nv_bfloat16* __restrict__ Bh, const __nv_bfloat16* __restrict__ Bl,
    float* __restrict__ Cmat, const float* __restrict__ bias, const float* __restrict__ res,
    int N, int K, size_t strideB, size_t strideC, size_t strideR)
{
    __shared__ __nv_bfloat16 AHI[128 * 32], ALO[128 * 32];
    __shared__ __nv_bfloat16 BHI[128 * 32], BLO[128 * 32];
    const uint32_t sAH = s2u(AHI), sAL = s2u(ALO);
    const uint32_t sBH = s2u(BHI), sBL = s2u(BLO);

    const int t = threadIdx.x;
    const int warp = t >> 5, lane = t & 31;
    const int wm = warp & 3, wn = warp >> 2;
    const int m0w = wm * 32, n0w = wn * 64;
    const int n0 = blockIdx.x * 128, m0 = blockIdx.y * 128;
    float* Cp = Cmat + strideC * blockIdx.z;
    const float* Rp = RES ? (res + strideR * blockIdx.z) : nullptr;

    const int lr = t >> 1;
    const int le = (t & 1) * 16;       // element offset within 32-k chunk
    const int cb = (t & 1) * 32;       // byte offset
    const __nv_bfloat16* pAh = Ah + (size_t)(m0 + lr) * K + le;
    const __nv_bfloat16* pAl = Al + (size_t)(m0 + lr) * K + le;
    const __nv_bfloat16* pBh = Bh + strideB * blockIdx.z + (size_t)(n0 + lr) * K + le;
    const __nv_bfloat16* pBl = Bl + strideB * blockIdx.z + (size_t)(n0 + lr) * K + le;

    const int brow = (lane & 7) + ((lane >> 4) << 3);
    const int bcol = ((lane >> 3) & 1) * 16;

    float acc[2][8][4] = {};
    uint4 rah[2], ral[2], rbh[2], rbl[2];

    // prefetch chunk 0
    rah[0] = *(const uint4*)(pAh);     rah[1] = *(const uint4*)(pAh + 8);
    ral[0] = *(const uint4*)(pAl);     ral[1] = *(const uint4*)(pAl + 8);
    rbh[0] = *(const uint4*)(pBh);     rbh[1] = *(const uint4*)(pBh + 8);
    rbl[0] = *(const uint4*)(pBl);     rbl[1] = *(const uint4*)(pBl + 8);

    for (int k0 = 0; k0 < K; k0 += 32) {
        // stage current chunk
        *(uint4*)((char*)AHI + GSW(lr * 64 + cb))      = rah[0];
        *(uint4*)((char*)AHI + GSW(lr * 64 + cb + 16)) = rah[1];
        *(uint4*)((char*)ALO + GSW(lr * 64 + cb))      = ral[0];
        *(uint4*)((char*)ALO + GSW(lr * 64 + cb + 16)) = ral[1];
        *(uint4*)((char*)BHI + GSW(lr * 64 + cb))      = rbh[0];
        *(uint4*)((char*)BHI + GSW(lr * 64 + cb + 16)) = rbh[1];
        *(uint4*)((char*)BLO + GSW(lr * 64 + cb))      = rbl[0];
        *(uint4*)((char*)BLO + GSW(lr * 64 + cb + 16)) = rbl[1];
        __syncthreads();

        // prefetch next chunk (overlaps with compute below)
        if (k0 + 32 < K) {
            int kn = k0 + 32;
            rah[0] = *(const uint4*)(pAh + kn);     rah[1] = *(const uint4*)(pAh + kn + 8);
            ral[0] = *(const uint4*)(pAl + kn);     ral[1] = *(const uint4*)(pAl + kn + 8);
            rbh[0] = *(const uint4*)(pBh + kn);     rbh[1] = *(const uint4*)(pBh + kn + 8);
            rbl[0] = *(const uint4*)(pBl + kn);     rbl[1] = *(const uint4*)(pBl + kn + 8);
        }

        #pragma unroll
        for (int kt = 0; kt < 2; kt++) {
            uint32_t ah[2][4], al[2][4];
            #pragma unroll
            for (int mi = 0; mi < 2; mi++) {
                uint32_t off = GSW((m0w + mi * 16 + (lane & 15)) * 64 + kt * 32 + (lane >> 4) * 16);
                ldsm4(ah[mi], sAH + off);
                ldsm4(al[mi], sAL + off);
            }
            #pragma unroll
            for (int nb = 0; nb < 4; nb++) {
                uint32_t bh[4], bl[4];
                uint32_t off = GSW((n0w + nb * 16 + brow) * 64 + kt * 32 + bcol);
                ldsm4(bh, sBH + off);
                ldsm4(bl, sBL + off);
                #pragma unroll
                for (int mi = 0; mi < 2; mi++) {
                    mma16816(acc[mi][2 * nb],     ah[mi], bh);
                    mma16816(acc[mi][2 * nb + 1], ah[mi], bh + 2);
                    mma16816(acc[mi][2 * nb],     ah[mi], bl);
                    mma16816(acc[mi][2 * nb + 1], ah[mi], bl + 2);
                    mma16816(acc[mi][2 * nb],     al[mi], bh);
                    mma16816(acc[mi][2 * nb + 1], al[mi], bh + 2);
                }
            }
        }
        __syncthreads();
    }

    // ---- epilogue
    #pragma unroll
    for (int mi = 0; mi < 2; mi++) {
        int r0 = m0 + m0w + mi * 16 + (lane >> 2);
        float b0 = bias[r0], b1 = bias[r0 + 8];
        #pragma unroll
        for (int nb = 0; nb < 8; nb++) {
            int col = n0 + n0w + nb * 8 + (lane & 3) * 2;
            float2 v0 = { acc[mi][nb][0] + b0, acc[mi][nb][1] + b0 };
            float2 v1 = { acc[mi][nb][2] + b1, acc[mi][nb][3] + b1 };
            if (CLIP) {
                v0.x = fminf(10.f, fmaxf(-10.f, v0.x));
                v0.y = fminf(10.f, fmaxf(-10.f, v0.y));
                v1.x = fminf(10.f, fmaxf(-10.f, v1.x));
                v1.y = fminf(10.f, fmaxf(-10.f, v1.y));
            }
            if (RES) {
                float2 r0v = *(const float2*)(Rp + (size_t)r0 * N + col);
                float2 r1v = *(const float2*)(Rp + (size_t)(r0 + 8) * N + col);
                v0.x += r0v.x; v0.y += r0v.y;
                v1.x += r1v.x; v1.y += r1v.y;
            }
            *(float2*)(Cp + (size_t)r0 * N + col) = v0;
            *(float2*)(Cp + (size_t)(r0 + 8) * N + col) = v1;
        }
    }
}

// ---------------------------------------------------------------------------
// Flash attention on mma.sync bf16 (pre-split inputs, bf16 attT output)
// ---------------------------------------------------------------------------
#define AQHI 0
#define AQLO 16384
#define AKHI 32768
#define AKLO 40960
#define AVHI 49152
#define AVLO 57344
#define ATTN_SMEM 65536

__global__ __launch_bounds__(256) void attn_mma_kernel(
    const __nv_bfloat16* __restrict__ qkTh, const __nv_bfloat16* __restrict__ qkTl,
    const __nv_bfloat16* __restrict__ vh,   const __nv_bfloat16* __restrict__ vl,
    __nv_bfloat16* __restrict__ aTh,        __nv_bfloat16* __restrict__ aTl)
{
    extern __shared__ char sm[];
    const uint32_t sb = s2u(sm);
    const int tid = threadIdx.x;
    const int w = tid >> 5, lane = tid & 31;
    const int b = blockIdx.z, h = blockIdx.y;
    const int i0 = blockIdx.x * 128;

    // ---- Q tiles hi/lo: [128i][64d], direct bf16 copy
    {
        int row = tid >> 1, eo = (tid & 1) * 32;
        const __nv_bfloat16* qh = qkTh + ((size_t)(b * 16 + h) * L_DIM + i0 + row) * HDIM + eo;
        const __nv_bfloat16* ql = qkTl + ((size_t)(b * 16 + h) * L_DIM + i0 + row) * HDIM + eo;
        #pragma unroll
        for (int u = 0; u < 4; u++) {
            *(uint4*)(sm + AQHI + SW(row * 128 + eo * 2 + 16 * u)) = *(const uint4*)(qh + 8 * u);
            *(uint4*)(sm + AQLO + SW(row * 128 + eo * 2 + 16 * u)) = *(const uint4*)(ql + 8 * u);
        }
    }
    __syncthreads();

    // ---- Q a-fragments (persistent)
    uint32_t qh[4][4], ql[4][4];
    {
        const int row = w * 16 + (lane & 15);
        const int colb = (lane >> 4) * 16;
        #pragma unroll
        for (int kt = 0; kt < 4; kt++) {
            uint32_t off = SW(row * 128 + kt * 32 + colb);
            ldsm4(qh[kt], sb + AQHI + off);
            ldsm4(ql[kt], sb + AQLO + off);
        }
    }

    const int brow = (lane & 7) + ((lane >> 4) << 3);
    const int bcol = ((lane >> 3) & 1) * 16;

    const float K1 = 0.125f * 1.44269504f;
    const float LIM = 10.0f * 1.44269504f;

    float oc[8][4] = {};
    float racc0 = 0.f, racc1 = 0.f;

    // loader mapping: K tile [64j][64d], V tile [64d][64j]
    const int krow = tid >> 2, keo = (tid & 3) * 16;
    const __nv_bfloat16* kbh = qkTh + ((size_t)(b * 16 + 8 + h) * L_DIM) * HDIM;
    const __nv_bfloat16* kbl = qkTl + ((size_t)(b * 16 + 8 + h) * L_DIM) * HDIM;
    const __nv_bfloat16* vbh = vh + ((size_t)b * C_DIM + h * 64 + krow) * L_DIM;
    const __nv_bfloat16* vbl = vl + ((size_t)b * C_DIM + h * 64 + krow) * L_DIM;

    for (int t = 0; t < 32; t++) {
        const int j0 = t * 64;
        __syncthreads();   // previous iteration's ldsm reads done

        {
            const __nv_bfloat16* ksh = kbh + (size_t)(j0 + krow) * HDIM + keo;
            const __nv_bfloat16* ksl = kbl + (size_t)(j0 + krow) * HDIM + keo;
            *(uint4*)(sm + AKHI + SW(krow * 128 + keo * 2))      = *(const uint4*)(ksh);
            *(uint4*)(sm + AKHI + SW(krow * 128 + keo * 2 + 16)) = *(const uint4*)(ksh + 8);
            *(uint4*)(sm + AKLO + SW(krow * 128 + keo * 2))      = *(const uint4*)(ksl);
            *(uint4*)(sm + AKLO + SW(krow * 128 + keo * 2 + 16)) = *(const uint4*)(ksl + 8);
            const __nv_bfloat16* vsh = vbh + j0 + keo;
            const __nv_bfloat16* vsl = vbl + j0 + keo;
            *(uint4*)(sm + AVHI + SW(krow * 128 + keo * 2))      = *(const uint4*)(vsh);
            *(uint4*)(sm + AVHI + SW(krow * 128 + keo * 2 + 16)) = *(const uint4*)(vsh + 8);
            *(uint4*)(sm + AVLO + SW(krow * 128 + keo * 2))      = *(const uint4*)(vsl);
            *(uint4*)(sm + AVLO + SW(krow * 128 + keo * 2 + 16)) = *(const uint4*)(vsl + 8);
        }
        __syncthreads();

        // ---- S = Q K^T
        float sc[8][4] = {};
        #pragma unroll
        for (int dt = 0; dt < 4; dt++) {
            #pragma unroll
            for (int jb = 0; jb < 4; jb++) {
                uint32_t kh[4], kl[4];
                uint32_t off = SW((jb * 16 + brow) * 128 + dt * 32 + bcol);
                ldsm4(kh, sb + AKHI + off);
                ldsm4(kl, sb + AKLO + off);
                mma16816(sc[2 * jb],     qh[dt], kh);
                mma16816(sc[2 * jb + 1], qh[dt], kh + 2);
                mma16816(sc[2 * jb],     qh[dt], kl);
                mma16816(sc[2 * jb + 1], qh[dt], kl + 2);
                mma16816(sc[2 * jb],     ql[dt], kh);
                mma16816(sc[2 * jb + 1], ql[dt], kh + 2);
            }
        }

        // ---- softmax numerator
        #pragma unroll
        for (int nt = 0; nt < 8; nt++) {
            #pragma unroll
            for (int k = 0; k < 4; k++) {
                float y = sc[nt][k] * K1;
                y = fminf(LIM, fmaxf(-LIM, y));
                float p = exp2_poly(y);
                sc[nt][k] = p;
                if (k < 2) racc0 += p; else racc1 += p;
            }
        }

        // ---- pack P fragments from registers
        uint32_t ph[4][4], pl[4][4];
        #pragma unroll
        for (int q = 0; q < 4; q++) {
            __nv_bfloat16 h0, l0, h1, l1;
            split_bf(sc[2 * q][0], h0, l0); split_bf(sc[2 * q][1], h1, l1);
            ph[q][0] = packb(h0, h1); pl[q][0] = packb(l0, l1);
            split_bf(sc[2 * q][2], h0, l0); split_bf(sc[2 * q][3], h1, l1);
            ph[q][1] = packb(h0, h1); pl[q][1] = packb(l0, l1);
            split_bf(sc[2 * q + 1][0], h0, l0); split_bf(sc[2 * q + 1][1], h1, l1);
            ph[q][2] = packb(h0, h1); pl[q][2] = packb(l0, l1);
            split_bf(sc[2 * q + 1][2], h0, l0); split_bf(sc[2 * q + 1][3], h1, l1);
            ph[q][3] = packb(h0, h1); pl[q][3] = packb(l0, l1);
        }

        // ---- O += P V^T
        #pragma unroll
        for (int kt = 0; kt < 4; kt++) {
            #pragma unroll
            for (int db = 0; db < 4; db++) {
                uint32_t vvh[4], vvl[4];
                uint32_t off = SW((db * 16 + brow) * 128 + kt * 32 + bcol);
                ldsm4(vvh, sb + AVHI + off);
                ldsm4(vvl, sb + AVLO + off);
                mma16816(oc[2 * db],     ph[kt], vvh);
                mma16816(oc[2 * db + 1], ph[kt], vvh + 2);
                mma16816(oc[2 * db],     ph[kt], vvl);
                mma16816(oc[2 * db + 1], ph[kt], vvl + 2);
                mma16816(oc[2 * db],     pl[kt], vvh);
                mma16816(oc[2 * db + 1], pl[kt], vvh + 2);
            }
        }
    }

    // ---- row denominators (quad reduce)
    racc0 += __shfl_xor_sync(0xffffffffu, racc0, 1);
    racc0 += __shfl_xor_sync(0xffffffffu, racc0, 2);
    racc1 += __shfl_xor_sync(0xffffffffu, racc1, 1);
    racc1 += __shfl_xor_sync(0xffffffffu, racc1, 2);
    const float inv0 = 1.0f / racc0;
    const float inv1 = 1.0f / racc1;

    // ---- write att^T hi/lo bf16: [b][l][c], c = h*64 + d
    const int ibase = i0 + w * 16 + (lane >> 2);
    const size_t rowbase = ((size_t)b * L_DIM + ibase) * C_DIM + h * 64;
    #pragma unroll
    for (int nt = 0; nt < 8; nt++) {
        int d = nt * 8 + 2 * (lane & 3);
        float a0 = oc[nt][0] * inv0, a1 = oc[nt][1] * inv0;
        float a2 = oc[nt][2] * inv1, a3 = oc[nt][3] * inv1;
        __nv_bfloat16 h0, l0, h1, l1;
        split_bf(a0, h0, l0); split_bf(a1, h1, l1);
        *(uint32_t*)(aTh + rowbase + d) = packb(h0, h1);
        *(uint32_t*)(aTl + rowbase + d) = packb(l0, l1);
        split_bf(a2, h0, l0); split_bf(a3, h1, l1);
        *(uint32_t*)(aTh + rowbase + (size_t)8 * C_DIM + d) = packb(h0, h1);
        *(uint32_t*)(aTl + rowbase + (size_t)8 * C_DIM + d) = packb(l0, l1);
    }
}

// ---------------------------------------------------------------------------
// GroupNorm (proven)
// ---------------------------------------------------------------------------
__global__ __launch_bounds__(256) void gn_kernel(
    const float* __restrict__ z, const float* __restrict__ gamma,
    const float* __restrict__ beta, float* __restrict__ outp)
{
    const int bg = blockIdx.x;
    const int b = bg >> 5, g = bg & 31;
    const float* zp = z + ((size_t)b * C_DIM + g * 16) * L_DIM;
    float* op = outp + ((size_t)b * C_DIM + g * 16) * L_DIM;
    const int t = threadIdx.x;

    float s = 0.f, ss = 0.f;
    const float4* z4 = (const float4*)zp;
    for (int i = t; i < 8192; i += 256) {
        float4 v = z4[i];
        s  += v.x + v.y + v.z + v.w;
        ss += v.x * v.x + v.y * v.y + v.z * v.z + v.w * v.w;
    }
    __shared__ float rs[8], rss[8];
    __shared__ float smu, srstd;
    #pragma unroll
    for (int o = 16; o; o >>= 1) {
        s  += __shfl_xor_sync(0xffffffffu, s, o);
        ss += __shfl_xor_sync(0xffffffffu, ss, o);
    }
    if ((t & 31) == 0) { rs[t >> 5] = s; rss[t >> 5] = ss; }
    __syncthreads();
    if (t == 0) {
        float ts = 0.f, tss = 0.f;
        #pragma unroll
        for (int wv = 0; wv < 8; wv++) { ts += rs[wv]; tss += rss[wv]; }
        float mu = ts * (1.f / 32768.f);
        float var = tss * (1.f / 32768.f) - mu * mu;
        smu = mu;
        srstd = rsqrtf(var + 1e-5f);
    }
    __syncthreads();
    const float mu = smu, rstd = srstd;
    float4* o4 = (float4*)op;
    for (int i = t; i < 8192; i += 256) {
        int ch = g * 16 + (i >> 9);
        float ga = gamma[ch] * rstd;
        float be = beta[ch];
        float4 v = z4[i];
        v.x = (v.x - mu) * ga + be;
        v.y = (v.y - mu) * ga + be;
        v.z = (v.z - mu) * ga + be;
        v.w = (v.w - mu) * ga + be;
        o4[i] = v;
    }
}

// ---------------------------------------------------------------------------
extern "C" void kernel_launch(void* const* d_in, const int* in_sizes, int n_in,
                              void* d_out, int out_size)
{
    const float* x     = (const float*)d_in[0];
    const float* Wqkv  = (const float*)d_in[1];
    const float* bqkv  = (const float*)d_in[2];
    const float* Wproj = (const float*)d_in[3];
    const float* bproj = (const float*)d_in[4];
    const float* gamma = (const float*)d_in[5];
    const float* beta  = (const float*)d_in[6];
    float* out = (float*)d_out;

    float *qkv, *zbuf;
    __nv_bfloat16 *xTh, *xTl, *qkTh, *qkTl, *vh, *vl, *aTh, *aTl, *wqh, *wql, *wph, *wpl;
    cudaGetSymbolAddress((void**)&qkv,  g_qkv);
    cudaGetSymbolAddress((void**)&zbuf, g_z);
    cudaGetSymbolAddress((void**)&xTh,  g_xTh);
    cudaGetSymbolAddress((void**)&xTl,  g_xTl);
    cudaGetSymbolAddress((void**)&qkTh, g_qkTh);
    cudaGetSymbolAddress((void**)&qkTl, g_qkTl);
    cudaGetSymbolAddress((void**)&vh,   g_vh);
    cudaGetSymbolAddress((void**)&vl,   g_vl);
    cudaGetSymbolAddress((void**)&aTh,  g_aTh);
    cudaGetSymbolAddress((void**)&aTl,  g_aTl);
    cudaGetSymbolAddress((void**)&wqh,  g_wqh);
    cudaGetSymbolAddress((void**)&wql,  g_wql);
    cudaGetSymbolAddress((void**)&wph,  g_wph);
    cudaGetSymbolAddress((void**)&wpl,  g_wpl);

    cudaFuncSetAttribute(attn_mma_kernel, cudaFuncAttributeMaxDynamicSharedMemorySize, ATTN_SMEM);

    // pre-split inputs
    tsplit_x_kernel<<<dim3(16, 8, BATCH), 256>>>(x, xTh, xTl);
    esplit_kernel<<<(3 * C_DIM * C_DIM / 4 + 255) / 256, 256>>>(Wqkv, wqh, wql, 3 * C_DIM * C_DIM / 4);
    esplit_kernel<<<(C_DIM * C_DIM / 4 + 255) / 256, 256>>>(Wproj, wph, wpl, C_DIM * C_DIM / 4);

    // qkv = Wqkv @ x + bqkv, clipped
    mma_gemm_kernel<true, false><<<dim3(16, 12, BATCH), 256>>>(
        wqh, wql, xTh, xTl, qkv, bqkv, nullptr, L_DIM, C_DIM, (size_t)CL, (size_t)3 * CL, 0);

    // split qkv for attention
    tsplit_qk_kernel<<<dim3(16, 16, BATCH), 256>>>(qkv, qkTh, qkTl);
    for (int b = 0; b < BATCH; b++) {
        esplit_kernel<<<CL / 4 / 256, 256>>>(qkv + ((size_t)3 * b + 2) * CL, vh + (size_t)b * CL, vl + (size_t)b * CL, CL / 4);
    }

    // attention -> att^T hi/lo bf16
    attn_mma_kernel<<<dim3(16, HEADS, BATCH), 256, ATTN_SMEM>>>(qkTh, qkTl, vh, vl, aTh, aTl);

    // z = Wproj @ att + bproj + x
    mma_gemm_kernel<false, true><<<dim3(16, 4, BATCH), 256>>>(
        wph, wpl, aTh, aTl, zbuf, bproj, x, L_DIM, C_DIM, (size_t)CL, (size_t)CL, (size_t)CL);

    // out = groupnorm(z)
    gn_kernel<<<dim3(BATCH * 32), 256>>>(zbuf, gamma, beta, out);
}

// round 12
// speedup vs baseline: 2.7864x; 1.0529x over previous
#include <cuda_runtime.h>
#include <cuda_bf16.h>
#include <cstdint>

#define C_DIM 512
#define L_DIM 2048
#define BATCH 4
#define HEADS 8
#define HDIM 64
#define CL (C_DIM * L_DIM)

// ---------------------------------------------------------------------------
// Helpers
// ---------------------------------------------------------------------------
__device__ __forceinline__ uint32_t s2u(const void* p) {
    uint32_t a;
    asm("{ .reg .u64 t; cvta.to.shared.u64 t, %1; cvt.u32.u64 %0, t; }" : "=r"(a) : "l"(p));
    return a;
}
__device__ __forceinline__ void ldsm4(uint32_t* r, uint32_t a) {
    asm volatile("ldmatrix.sync.aligned.m8n8.x4.shared.b16 {%0,%1,%2,%3}, [%4];"
                 : "=r"(r[0]), "=r"(r[1]), "=r"(r[2]), "=r"(r[3]) : "r"(a));
}
__device__ __forceinline__ void mma16816(float* c, const uint32_t* a, const uint32_t* b) {
    asm volatile("mma.sync.aligned.m16n8k16.row.col.f32.bf16.bf16.f32 "
                 "{%0,%1,%2,%3}, {%4,%5,%6,%7}, {%8,%9}, {%0,%1,%2,%3};"
                 : "+f"(c[0]), "+f"(c[1]), "+f"(c[2]), "+f"(c[3])
                 : "r"(a[0]), "r"(a[1]), "r"(a[2]), "r"(a[3]), "r"(b[0]), "r"(b[1]));
}
#define CP16(dst, src)  asm volatile("cp.async.cg.shared.global [%0], [%1], 16;" :: "r"(dst), "l"(src))
#define CPCOMMIT()      asm volatile("cp.async.commit_group;")
#define CPWAIT1()       asm volatile("cp.async.wait_group 1;" ::: "memory")
#define SW(x)  ((x) ^ (((x) >> 3) & 0x70))   // 128B-row swizzle
#define GSW(x) ((x) ^ (((x) >> 3) & 0x30))   // 64B-row swizzle
__device__ __forceinline__ void split_bf(float x, __nv_bfloat16& h, __nv_bfloat16& l) {
    h = __float2bfloat16(x);
    l = __float2bfloat16(x - __bfloat162float(h));
}
__device__ __forceinline__ uint32_t packb(__nv_bfloat16 a, __nv_bfloat16 b) {
    __nv_bfloat162 t(a, b);
    return *(uint32_t*)&t;
}
// exp2 via FFMA/ALU only (no MUFU). |y| <= 14.5 guaranteed by clip.
__device__ __forceinline__ float exp2_poly(float y) {
    float r = y + 12582912.f;
    int n = __float_as_int(r) - 0x4B400000;
    float f = y - (r - 12582912.f);
    float p = 0.0013333558f;
    p = p * f + 0.0096181291f;
    p = p * f + 0.0555041087f;
    p = p * f + 0.2402265069f;
    p = p * f + 0.6931471825f;
    p = p * f + 1.0f;
    return __int_as_float(__float_as_int(p) + (n << 23));
}

// ---------------------------------------------------------------------------
// Scratch
// ---------------------------------------------------------------------------
__device__ float g_qkv[BATCH * 3 * CL];
__device__ float g_z[BATCH * CL];
__device__ __nv_bfloat16 g_xTh[BATCH * CL], g_xTl[BATCH * CL];
__device__ __nv_bfloat16 g_qkTh[BATCH * 16 * L_DIM * HDIM], g_qkTl[BATCH * 16 * L_DIM * HDIM];
__device__ __nv_bfloat16 g_vh[BATCH * CL], g_vl[BATCH * CL];
__device__ __nv_bfloat16 g_aTh[BATCH * CL], g_aTl[BATCH * CL];
__device__ __nv_bfloat16 g_wqh[3 * C_DIM * C_DIM], g_wql[3 * C_DIM * C_DIM];
__device__ __nv_bfloat16 g_wph[C_DIM * C_DIM], g_wpl[C_DIM * C_DIM];

// ---------------------------------------------------------------------------
// Elementwise fp32 -> bf16 hi/lo split
// ---------------------------------------------------------------------------
__global__ __launch_bounds__(256) void esplit_kernel(
    const float* __restrict__ s, __nv_bfloat16* __restrict__ dh,
    __nv_bfloat16* __restrict__ dl, int n4)
{
    int i = blockIdx.x * 256 + threadIdx.x;
    if (i >= n4) return;
    float4 v = ((const float4*)s)[i];
    __nv_bfloat16 h0, l0, h1, l1, h2, l2, h3, l3;
    split_bf(v.x, h0, l0); split_bf(v.y, h1, l1);
    split_bf(v.z, h2, l2); split_bf(v.w, h3, l3);
    uint2 wh = { packb(h0, h1), packb(h2, h3) };
    uint2 wl = { packb(l0, l1), packb(l2, l3) };
    ((uint2*)dh)[i] = wh;
    ((uint2*)dl)[i] = wl;
}

// ---------------------------------------------------------------------------
// Transpose + split tile helper (fp32 [64r][128c] -> bf16 hi/lo [128][64])
// ---------------------------------------------------------------------------
__device__ __forceinline__ void tsplit_tile(
    const float* src, __nv_bfloat16* dh, __nv_bfloat16* dl, int dstStride)
{
    __shared__ __nv_bfloat16 th[128 * 64], tl[128 * 64];
    const int t = threadIdx.x;
    {
        int r = t >> 2, cb = (t & 3) * 32;
        const float4* s4 = (const float4*)(src + (size_t)r * L_DIM + cb);
        #pragma unroll
        for (int u = 0; u < 8; u++) {
            float4 v = s4[u];
            float vv[4] = {v.x, v.y, v.z, v.w};
            #pragma unroll
            for (int e = 0; e < 4; e++) {
                int c = cb + 4 * u + e;
                __nv_bfloat16 hb, lb; split_bf(vv[e], hb, lb);
                th[c * 64 + r] = hb;
                tl[c * 64 + r] = lb;
            }
        }
    }
    __syncthreads();
    {
        int l = t >> 1, eo = (t & 1) * 32;
        __nv_bfloat16* dph = dh + (size_t)l * dstStride + eo;
        __nv_bfloat16* dpl = dl + (size_t)l * dstStride + eo;
        #pragma unroll
        for (int u = 0; u < 4; u++) {
            *(uint4*)(dph + 8 * u) = *(uint4*)&th[l * 64 + eo + 8 * u];
            *(uint4*)(dpl + 8 * u) = *(uint4*)&tl[l * 64 + eo + 8 * u];
        }
    }
}

__global__ __launch_bounds__(256) void tsplit_x_kernel(
    const float* __restrict__ x, __nv_bfloat16* __restrict__ dh, __nv_bfloat16* __restrict__ dl)
{
    const int lc = blockIdx.x, cc = blockIdx.y, b = blockIdx.z;
    const float* src = x + ((size_t)b * C_DIM + cc * 64) * L_DIM + lc * 128;
    size_t doff = ((size_t)b * L_DIM + lc * 128) * C_DIM + cc * 64;
    tsplit_tile(src, dh + doff, dl + doff, C_DIM);
}

__global__ __launch_bounds__(256) void tsplit_qk_kernel(
    const float* __restrict__ qkv, __nv_bfloat16* __restrict__ dh, __nv_bfloat16* __restrict__ dl)
{
    const int lc = blockIdx.x, hh = blockIdx.y, b = blockIdx.z;
    const float* src = qkv + ((size_t)b * 3 * C_DIM + hh * 64) * L_DIM + lc * 128;
    size_t doff = ((size_t)(b * 16 + hh) * L_DIM + lc * 128) * HDIM;
    tsplit_tile(src, dh + doff, dl + doff, HDIM);
}

// ---------------------------------------------------------------------------
// Tensor-core GEMM, cp.async 3-stage: C[b][m][n] = sum_k A[m][k]*B[b][n][k]
// BM=128, BN=256, BK=32, 256 threads, warp grid 2x4, warp tile 64x64.
// Stage (48KB): AHI 8KB | ALO 8KB | BHI 16KB | BLO 16KB. 3 stages = 144KB.
// ---------------------------------------------------------------------------
#define GSTG 49152
#define GOFF_AL 8192
#define GOFF_BH 16384
#define GOFF_BL 32768
#define GEMM_SMEM (3 * GSTG)

template<bool CLIP, bool RES>
__global__ __launch_bounds__(256) void mma_gemm_kernel(
    const __nv_bfloat16* __restrict__ Ah, const __nv_bfloat16* __restrict__ Al,
    const __nv_bfloat16* __restrict__ Bh, const __nv_bfloat16* __restrict__ Bl,
    float* __restrict__ Cmat, const float* __restrict__ bias, const float* __restrict__ res,
    int N, int K, size_t strideB, size_t strideC, size_t strideR)
{
    extern __shared__ char gsm[];
    const uint32_t sb = s2u(gsm);

    const int t = threadIdx.x;
    const int warp = t >> 5, lane = t & 31;
    const int wm = warp & 1, wn = warp >> 1;
    const int m0w = wm * 64, n0w = wn * 64;
    const int n0 = blockIdx.x * 256, m0 = blockIdx.y * 128;
    float* Cp = Cmat + strideC * blockIdx.z;
    const float* Rp = RES ? (res + strideR * blockIdx.z) : nullptr;

    // loader mapping: A 128 rows x 64B (2 chunks/thr), B 256 rows x 64B (4 chunks/thr)
    const int ar = t >> 1, aco = (t & 1) * 32;
    const int br = t;
    const char* pAh = (const char*)(Ah + (size_t)(m0 + ar) * K) + aco;
    const char* pAl = (const char*)(Al + (size_t)(m0 + ar) * K) + aco;
    const char* pBh = (const char*)(Bh + strideB * blockIdx.z + (size_t)(n0 + br) * K);
    const char* pBl = (const char*)(Bl + strideB * blockIdx.z + (size_t)(n0 + br) * K);
    const uint32_t dA0 = GSW(ar * 64 + aco), dA1 = GSW(ar * 64 + aco + 16);
    uint32_t dB[4];
    #pragma unroll
    for (int u = 0; u < 4; u++) dB[u] = GSW(br * 64 + u * 16);

    const int brow = (lane & 7) + ((lane >> 4) << 3);
    const int bcol = ((lane >> 3) & 1) * 16;

    const int NCH = K >> 5;   // 32-k chunks

    // prologue: stages 0,1
    #pragma unroll
    for (int c = 0; c < 2; c++) {
        uint32_t base = sb + c * GSTG;
        size_t go = (size_t)c * 64;
        CP16(base + dA0, pAh + go); CP16(base + dA1, pAh + go + 16);
        CP16(base + GOFF_AL + dA0, pAl + go); CP16(base + GOFF_AL + dA1, pAl + go + 16);
        #pragma unroll
        for (int u = 0; u < 4; u++) {
            CP16(base + GOFF_BH + dB[u], pBh + go + u * 16);
            CP16(base + GOFF_BL + dB[u], pBl + go + u * 16);
        }
        CPCOMMIT();
    }

    float acc[4][8][4] = {};
    int stg = 0, nstg = 2;

    for (int c = 0; c < NCH; c++) {
        CPWAIT1();
        __syncthreads();

        if (c + 2 < NCH) {
            uint32_t base = sb + nstg * GSTG;
            size_t go = (size_t)(c + 2) * 64;
            CP16(base + dA0, pAh + go); CP16(base + dA1, pAh + go + 16);
            CP16(base + GOFF_AL + dA0, pAl + go); CP16(base + GOFF_AL + dA1, pAl + go + 16);
            #pragma unroll
            for (int u = 0; u < 4; u++) {
                CP16(base + GOFF_BH + dB[u], pBh + go + u * 16);
                CP16(base + GOFF_BL + dB[u], pBl + go + u * 16);
            }
            CPCOMMIT();
        }
        nstg = nstg == 2 ? 0 : nstg + 1;

        const uint32_t sA = sb + stg * GSTG;
        #pragma unroll
        for (int kt = 0; kt < 2; kt++) {
            uint32_t ah[4][4], al[4][4];
            #pragma unroll
            for (int mi = 0; mi < 4; mi++) {
                uint32_t off = GSW((m0w + mi * 16 + (lane & 15)) * 64 + kt * 32 + (lane >> 4) * 16);
                ldsm4(ah[mi], sA + off);
                ldsm4(al[mi], sA + GOFF_AL + off);
            }
            #pragma unroll
            for (int nb = 0; nb < 4; nb++) {
                uint32_t bh[4], bl[4];
                uint32_t off = GSW((n0w + nb * 16 + brow) * 64 + kt * 32 + bcol);
                ldsm4(bh, sA + GOFF_BH + off);
                ldsm4(bl, sA + GOFF_BL + off);
                #pragma unroll
                for (int mi = 0; mi < 4; mi++) {
                    mma16816(acc[mi][2 * nb],     ah[mi], bh);
                    mma16816(acc[mi][2 * nb + 1], ah[mi], bh + 2);
                    mma16816(acc[mi][2 * nb],     ah[mi], bl);
                    mma16816(acc[mi][2 * nb + 1], ah[mi], bl + 2);
                    mma16816(acc[mi][2 * nb],     al[mi], bh);
                    mma16816(acc[mi][2 * nb + 1], al[mi], bh + 2);
                }
            }
        }
        stg = stg == 2 ? 0 : stg + 1;
    }

    // ---- epilogue
    #pragma unroll
    for (int mi = 0; mi < 4; mi++) {
        int r0 = m0 + m0w + mi * 16 + (lane >> 2);
        float b0 = bias[r0], b1 = bias[r0 + 8];
        #pragma unroll
        for (int nb = 0; nb < 8; nb++) {
            int col = n0 + n0w + nb * 8 + (lane & 3) * 2;
            float2 v0 = { acc[mi][nb][0] + b0, acc[mi][nb][1] + b0 };
            float2 v1 = { acc[mi][nb][2] + b1, acc[mi][nb][3] + b1 };
            if (CLIP) {
                v0.x = fminf(10.f, fmaxf(-10.f, v0.x));
                v0.y = fminf(10.f, fmaxf(-10.f, v0.y));
                v1.x = fminf(10.f, fmaxf(-10.f, v1.x));
                v1.y = fminf(10.f, fmaxf(-10.f, v1.y));
            }
            if (RES) {
                float2 r0v = *(const float2*)(Rp + (size_t)r0 * N + col);
                float2 r1v = *(const float2*)(Rp + (size_t)(r0 + 8) * N + col);
                v0.x += r0v.x; v0.y += r0v.y;
                v1.x += r1v.x; v1.y += r1v.y;
            }
            *(float2*)(Cp + (size_t)r0 * N + col) = v0;
            *(float2*)(Cp + (size_t)(r0 + 8) * N + col) = v1;
        }
    }
}

// ---------------------------------------------------------------------------
// Flash attention, cp.async 3-stage KV pipeline.
// smem: QHI 16KB | QLO 16KB | 3 x (KHI 8 | KLO 8 | VHI 8 | VLO 8)KB = 128KB
// ---------------------------------------------------------------------------
#define AQHI 0
#define AQLO 16384
#define AKV  32768
#define KVSTG 32768
#define OFF_KL 8192
#define OFF_VH 16384
#define OFF_VL 24576
#define ATTN_SMEM (AKV + 3 * KVSTG)

__global__ __launch_bounds__(256) void attn_mma_kernel(
    const __nv_bfloat16* __restrict__ qkTh, const __nv_bfloat16* __restrict__ qkTl,
    const __nv_bfloat16* __restrict__ vh,   const __nv_bfloat16* __restrict__ vl,
    __nv_bfloat16* __restrict__ aTh,        __nv_bfloat16* __restrict__ aTl)
{
    extern __shared__ char sm[];
    const uint32_t sb = s2u(sm);
    const int tid = threadIdx.x;
    const int w = tid >> 5, lane = tid & 31;
    const int b = blockIdx.z, h = blockIdx.y;
    const int i0 = blockIdx.x * 128;

    // ---- Q tiles hi/lo (direct bf16 copy, once)
    {
        int row = tid >> 1, eo = (tid & 1) * 32;
        const __nv_bfloat16* qh = qkTh + ((size_t)(b * 16 + h) * L_DIM + i0 + row) * HDIM + eo;
        const __nv_bfloat16* ql = qkTl + ((size_t)(b * 16 + h) * L_DIM + i0 + row) * HDIM + eo;
        #pragma unroll
        for (int u = 0; u < 4; u++) {
            *(uint4*)(sm + AQHI + SW(row * 128 + eo * 2 + 16 * u)) = *(const uint4*)(qh + 8 * u);
            *(uint4*)(sm + AQLO + SW(row * 128 + eo * 2 + 16 * u)) = *(const uint4*)(ql + 8 * u);
        }
    }

    // KV loader mapping: 64 rows x 128B, 2 chunks per thread per buffer
    const int krow = tid >> 2;
    const int kco = (tid & 3) * 32;
    const char* pKh = (const char*)(qkTh + ((size_t)(b * 16 + 8 + h) * L_DIM + krow) * HDIM) + kco;
    const char* pKl = (const char*)(qkTl + ((size_t)(b * 16 + 8 + h) * L_DIM + krow) * HDIM) + kco;
    const char* pVh = (const char*)(vh + ((size_t)b * C_DIM + h * 64 + krow) * L_DIM) + kco;
    const char* pVl = (const char*)(vl + ((size_t)b * C_DIM + h * 64 + krow) * L_DIM) + kco;
    const uint32_t dK0 = SW(krow * 128 + kco), dK1 = SW(krow * 128 + kco + 16);

    // prologue: issue KV tiles 0,1
    #pragma unroll
    for (int tt = 0; tt < 2; tt++) {
        uint32_t base = sb + AKV + tt * KVSTG;
        size_t goK = (size_t)tt * 64 * HDIM * 2;   // 8KB per tile along K rows
        size_t goV = (size_t)tt * 128;             // 64 elements along L
        CP16(base + dK0, pKh + goK); CP16(base + dK1, pKh + goK + 16);
        CP16(base + OFF_KL + dK0, pKl + goK); CP16(base + OFF_KL + dK1, pKl + goK + 16);
        CP16(base + OFF_VH + dK0, pVh + goV); CP16(base + OFF_VH + dK1, pVh + goV + 16);
        CP16(base + OFF_VL + dK0, pVl + goV); CP16(base + OFF_VL + dK1, pVl + goV + 16);
        CPCOMMIT();
    }
    __syncthreads();

    // ---- Q a-fragments (persistent)
    uint32_t qh[4][4], ql[4][4];
    {
        const int row = w * 16 + (lane & 15);
        const int colb = (lane >> 4) * 16;
        #pragma unroll
        for (int kt = 0; kt < 4; kt++) {
            uint32_t off = SW(row * 128 + kt * 32 + colb);
            ldsm4(qh[kt], sb + AQHI + off);
            ldsm4(ql[kt], sb + AQLO + off);
        }
    }

    const int brow = (lane & 7) + ((lane >> 4) << 3);
    const int bcol = ((lane >> 3) & 1) * 16;

    const float K1 = 0.125f * 1.44269504f;
    const float LIM = 10.0f * 1.44269504f;

    float oc[8][4] = {};
    float racc0 = 0.f, racc1 = 0.f;
    int stg = 0, nstg = 2;

    for (int t = 0; t < 32; t++) {
        CPWAIT1();
        __syncthreads();

        if (t + 2 < 32) {
            uint32_t base = sb + AKV + nstg * KVSTG;
            size_t goK = (size_t)(t + 2) * 64 * HDIM * 2;
            size_t goV = (size_t)(t + 2) * 128;
            CP16(base + dK0, pKh + goK); CP16(base + dK1, pKh + goK + 16);
            CP16(base + OFF_KL + dK0, pKl + goK); CP16(base + OFF_KL + dK1, pKl + goK + 16);
            CP16(base + OFF_VH + dK0, pVh + goV); CP16(base + OFF_VH + dK1, pVh + goV + 16);
            CP16(base + OFF_VL + dK0, pVl + goV); CP16(base + OFF_VL + dK1, pVl + goV + 16);
            CPCOMMIT();
        }
        nstg = nstg == 2 ? 0 : nstg + 1;

        const uint32_t sKV = sb + AKV + stg * KVSTG;

        // ---- S = Q K^T
        float sc[8][4] = {};
        #pragma unroll
        for (int dt = 0; dt < 4; dt++) {
            #pragma unroll
            for (int jb = 0; jb < 4; jb++) {
                uint32_t kh[4], kl[4];
                uint32_t off = SW((jb * 16 + brow) * 128 + dt * 32 + bcol);
                ldsm4(kh, sKV + off);
                ldsm4(kl, sKV + OFF_KL + off);
                mma16816(sc[2 * jb],     qh[dt], kh);
                mma16816(sc[2 * jb + 1], qh[dt], kh + 2);
                mma16816(sc[2 * jb],     qh[dt], kl);
                mma16816(sc[2 * jb + 1], qh[dt], kl + 2);
                mma16816(sc[2 * jb],     ql[dt], kh);
                mma16816(sc[2 * jb + 1], ql[dt], kh + 2);
            }
        }

        // ---- softmax numerator
        #pragma unroll
        for (int nt = 0; nt < 8; nt++) {
            #pragma unroll
            for (int k = 0; k < 4; k++) {
                float y = sc[nt][k] * K1;
                y = fminf(LIM, fmaxf(-LIM, y));
                float p = exp2_poly(y);
                sc[nt][k] = p;
                if (k < 2) racc0 += p; else racc1 += p;
            }
        }

        // ---- pack P fragments from registers
        uint32_t ph[4][4], pl[4][4];
        #pragma unroll
        for (int q = 0; q < 4; q++) {
            __nv_bfloat16 h0, l0, h1, l1;
            split_bf(sc[2 * q][0], h0, l0); split_bf(sc[2 * q][1], h1, l1);
            ph[q][0] = packb(h0, h1); pl[q][0] = packb(l0, l1);
            split_bf(sc[2 * q][2], h0, l0); split_bf(sc[2 * q][3], h1, l1);
            ph[q][1] = packb(h0, h1); pl[q][1] = packb(l0, l1);
            split_bf(sc[2 * q + 1][0], h0, l0); split_bf(sc[2 * q + 1][1], h1, l1);
            ph[q][2] = packb(h0, h1); pl[q][2] = packb(l0, l1);
            split_bf(sc[2 * q + 1][2], h0, l0); split_bf(sc[2 * q + 1][3], h1, l1);
            ph[q][3] = packb(h0, h1); pl[q][3] = packb(l0, l1);
        }

        // ---- O += P V^T
        #pragma unroll
        for (int kt = 0; kt < 4; kt++) {
            #pragma unroll
            for (int db = 0; db < 4; db++) {
                uint32_t vvh[4], vvl[4];
                uint32_t off = SW((db * 16 + brow) * 128 + kt * 32 + bcol);
                ldsm4(vvh, sKV + OFF_VH + off);
                ldsm4(vvl, sKV + OFF_VL + off);
                mma16816(oc[2 * db],     ph[kt], vvh);
                mma16816(oc[2 * db + 1], ph[kt], vvh + 2);
                mma16816(oc[2 * db],     ph[kt], vvl);
                mma16816(oc[2 * db + 1], ph[kt], vvl + 2);
                mma16816(oc[2 * db],     pl[kt], vvh);
                mma16816(oc[2 * db + 1], pl[kt], vvh + 2);
            }
        }
        stg = stg == 2 ? 0 : stg + 1;
    }

    // ---- row denominators (quad reduce)
    racc0 += __shfl_xor_sync(0xffffffffu, racc0, 1);
    racc0 += __shfl_xor_sync(0xffffffffu, racc0, 2);
    racc1 += __shfl_xor_sync(0xffffffffu, racc1, 1);
    racc1 += __shfl_xor_sync(0xffffffffu, racc1, 2);
    const float inv0 = 1.0f / racc0;
    const float inv1 = 1.0f / racc1;

    // ---- write att^T hi/lo bf16: [b][l][c], c = h*64 + d
    const int ibase = i0 + w * 16 + (lane >> 2);
    const size_t rowbase = ((size_t)b * L_DIM + ibase) * C_DIM + h * 64;
    #pragma unroll
    for (int nt = 0; nt < 8; nt++) {
        int d = nt * 8 + 2 * (lane & 3);
        float a0 = oc[nt][0] * inv0, a1 = oc[nt][1] * inv0;
        float a2 = oc[nt][2] * inv1, a3 = oc[nt][3] * inv1;
        __nv_bfloat16 h0, l0, h1, l1;
        split_bf(a0, h0, l0); split_bf(a1, h1, l1);
        *(uint32_t*)(aTh + rowbase + d) = packb(h0, h1);
        *(uint32_t*)(aTl + rowbase + d) = packb(l0, l1);
        split_bf(a2, h0, l0); split_bf(a3, h1, l1);
        *(uint32_t*)(aTh + rowbase + (size_t)8 * C_DIM + d) = packb(h0, h1);
        *(uint32_t*)(aTl + rowbase + (size_t)8 * C_DIM + d) = packb(l0, l1);
    }
}

// ---------------------------------------------------------------------------
// GroupNorm (proven)
// ---------------------------------------------------------------------------
__global__ __launch_bounds__(256) void gn_kernel(
    const float* __restrict__ z, const float* __restrict__ gamma,
    const float* __restrict__ beta, float* __restrict__ outp)
{
    const int bg = blockIdx.x;
    const int b = bg >> 5, g = bg & 31;
    const float* zp = z + ((size_t)b * C_DIM + g * 16) * L_DIM;
    float* op = outp + ((size_t)b * C_DIM + g * 16) * L_DIM;
    const int t = threadIdx.x;

    float s = 0.f, ss = 0.f;
    const float4* z4 = (const float4*)zp;
    for (int i = t; i < 8192; i += 256) {
        float4 v = z4[i];
        s  += v.x + v.y + v.z + v.w;
        ss += v.x * v.x + v.y * v.y + v.z * v.z + v.w * v.w;
    }
    __shared__ float rs[8], rss[8];
    __shared__ float smu, srstd;
    #pragma unroll
    for (int o = 16; o; o >>= 1) {
        s  += __shfl_xor_sync(0xffffffffu, s, o);
        ss += __shfl_xor_sync(0xffffffffu, ss, o);
    }
    if ((t & 31) == 0) { rs[t >> 5] = s; rss[t >> 5] = ss; }
    __syncthreads();
    if (t == 0) {
        float ts = 0.f, tss = 0.f;
        #pragma unroll
        for (int wv = 0; wv < 8; wv++) { ts += rs[wv]; tss += rss[wv]; }
        float mu = ts * (1.f / 32768.f);
        float var = tss * (1.f / 32768.f) - mu * mu;
        smu = mu;
        srstd = rsqrtf(var + 1e-5f);
    }
    __syncthreads();
    const float mu = smu, rstd = srstd;
    float4* o4 = (float4*)op;
    for (int i = t; i < 8192; i += 256) {
        int ch = g * 16 + (i >> 9);
        float ga = gamma[ch] * rstd;
        float be = beta[ch];
        float4 v = z4[i];
        v.x = (v.x - mu) * ga + be;
        v.y = (v.y - mu) * ga + be;
        v.z = (v.z - mu) * ga + be;
        v.w = (v.w - mu) * ga + be;
        o4[i] = v;
    }
}

// ---------------------------------------------------------------------------
extern "C" void kernel_launch(void* const* d_in, const int* in_sizes, int n_in,
                              void* d_out, int out_size)
{
    const float* x     = (const float*)d_in[0];
    const float* Wqkv  = (const float*)d_in[1];
    const float* bqkv  = (const float*)d_in[2];
    const float* Wproj = (const float*)d_in[3];
    const float* bproj = (const float*)d_in[4];
    const float* gamma = (const float*)d_in[5];
    const float* beta  = (const float*)d_in[6];
    float* out = (float*)d_out;

    float *qkv, *zbuf;
    __nv_bfloat16 *xTh, *xTl, *qkTh, *qkTl, *vh, *vl, *aTh, *aTl, *wqh, *wql, *wph, *wpl;
    cudaGetSymbolAddress((void**)&qkv,  g_qkv);
    cudaGetSymbolAddress((void**)&zbuf, g_z);
    cudaGetSymbolAddress((void**)&xTh,  g_xTh);
    cudaGetSymbolAddress((void**)&xTl,  g_xTl);
    cudaGetSymbolAddress((void**)&qkTh, g_qkTh);
    cudaGetSymbolAddress((void**)&qkTl, g_qkTl);
    cudaGetSymbolAddress((void**)&vh,   g_vh);
    cudaGetSymbolAddress((void**)&vl,   g_vl);
    cudaGetSymbolAddress((void**)&aTh,  g_aTh);
    cudaGetSymbolAddress((void**)&aTl,  g_aTl);
    cudaGetSymbolAddress((void**)&wqh,  g_wqh);
    cudaGetSymbolAddress((void**)&wql,  g_wql);
    cudaGetSymbolAddress((void**)&wph,  g_wph);
    cudaGetSymbolAddress((void**)&wpl,  g_wpl);

    cudaFuncSetAttribute(attn_mma_kernel, cudaFuncAttributeMaxDynamicSharedMemorySize, ATTN_SMEM);
    cudaFuncSetAttribute(mma_gemm_kernel<true, false>,  cudaFuncAttributeMaxDynamicSharedMemorySize, GEMM_SMEM);
    cudaFuncSetAttribute(mma_gemm_kernel<false, true>,  cudaFuncAttributeMaxDynamicSharedMemorySize, GEMM_SMEM);

    // pre-split inputs
    tsplit_x_kernel<<<dim3(16, 8, BATCH), 256>>>(x, xTh, xTl);
    esplit_kernel<<<(3 * C_DIM * C_DIM / 4 + 255) / 256, 256>>>(Wqkv, wqh, wql, 3 * C_DIM * C_DIM / 4);
    esplit_kernel<<<(C_DIM * C_DIM / 4 + 255) / 256, 256>>>(Wproj, wph, wpl, C_DIM * C_DIM / 4);

    // qkv = Wqkv @ x + bqkv, clipped
    mma_gemm_kernel<true, false><<<dim3(8, 12, BATCH), 256, GEMM_SMEM>>>(
        wqh, wql, xTh, xTl, qkv, bqkv, nullptr, L_DIM, C_DIM, (size_t)CL, (size_t)3 * CL, 0);

    // split qkv for attention
    tsplit_qk_kernel<<<dim3(16, 16, BATCH), 256>>>(qkv, qkTh, qkTl);
    for (int b = 0; b < BATCH; b++) {
        esplit_kernel<<<CL / 4 / 256, 256>>>(qkv + ((size_t)3 * b + 2) * CL, vh + (size_t)b * CL, vl + (size_t)b * CL, CL / 4);
    }

    // attention -> att^T hi/lo bf16
    attn_mma_kernel<<<dim3(16, HEADS, BATCH), 256, ATTN_SMEM>>>(qkTh, qkTl, vh, vl, aTh, aTl);

    // z = Wproj @ att + bproj + x
    mma_gemm_kernel<false, true><<<dim3(8, 4, BATCH), 256, GEMM_SMEM>>>(
        wph, wpl, aTh, aTl, zbuf, bproj, x, L_DIM, C_DIM, (size_t)CL, (size_t)CL, (size_t)CL);

    // out = groupnorm(z)
    gn_kernel<<<dim3(BATCH * 32), 256>>>(zbuf, gamma, beta, out);
}